// round 11
// baseline (speedup 1.0000x reference)
#include <cuda_runtime.h>
#include <cuda_fp16.h>
#include <mma.h>
using namespace nvcuda;

#define NN 50000
#define NPAD 50048            // 782 * 64, pad for wmma tiles
#define EE 800000
#define HH 256
#define BB 128
#define VV 4
#define CC 10
#define PH 512                // pair row width: 2 views * 256 feats
#define KC 32                 // gemm k-chunk
#define SCB 49                // scan blocks: 49*1024 >= NN

// ---- scratch (device globals; no allocation allowed) ----
__device__ int    g_degcnt[NN];
__device__ int    g_rowptr[NN+1];
__device__ int    g_fill[NN];
__device__ float  g_invdeg[NN];
__device__ int    g_col[EE];
__device__ int    g_counts[BB];
__device__ int    g_part[SCB];              // scan partials
__device__ float4 g_mask4[NN];              // transposed node masks
__device__ __half g_w1h[HH*HH];             // W1 fp16
__device__ __half g_z[NPAD*HH];             // (x*dropout) @ W1, fp16
__device__ __half g_pairs[2][(size_t)NN*PH]; // view pairs {0,1},{2,3}
__device__ __half g_ptmp[2][(size_t)NN*PH];  // ping-pong per pair
__device__ float  g_pool[VV*BB*HH];
__device__ float  g_probs[VV*BB*CC];

// ---------------------------------------------------------------------------
__global__ void k_zero(const float* __restrict__ W1) {
    int i = blockIdx.x * blockDim.x + threadIdx.x;
    if (i < NN) g_degcnt[i] = 0;
    if (i < BB) g_counts[i] = 0;
    if (i < VV*BB*HH) g_pool[i] = 0.f;
    if (i < HH*HH/4) {
        float4 w = *(const float4*)(W1 + i * 4);
        __half2 h[2];
        h[0] = __floats2half2_rn(w.x, w.y);
        h[1] = __floats2half2_rn(w.z, w.w);
        *(uint2*)(g_w1h + i * 4) = *(uint2*)h;
    }
}

// histogram over edge rows + batch counts + mask transpose, one launch
__global__ void k_hist(const int* __restrict__ ei, const int* __restrict__ batch,
                       const float* __restrict__ masks) {
    int e = blockIdx.x * blockDim.x + threadIdx.x;
    if (e < EE) {
        int r = ei[e];
        if ((unsigned)r < NN) atomicAdd(&g_degcnt[r], 1);
    }
    if (e < NN) {
        int b = batch[e];
        if ((unsigned)b < BB) atomicAdd(&g_counts[b], 1);
        g_mask4[e] = make_float4(masks[e], masks[NN + e], masks[2*NN + e], masks[3*NN + e]);
    }
}

// ---- 3-phase grid-wide exclusive scan of g_degcnt -------------------------
__global__ __launch_bounds__(1024) void k_scan_a() {
    __shared__ int wsum[32];
    int i = blockIdx.x * 1024 + threadIdx.x;
    int lane = threadIdx.x & 31, wid = threadIdx.x >> 5;
    int c = (i < NN) ? g_degcnt[i] : 0;
    int s = c;
    #pragma unroll
    for (int d = 16; d > 0; d >>= 1) s += __shfl_down_sync(0xffffffffu, s, d);
    if (lane == 0) wsum[wid] = s;
    __syncthreads();
    if (wid == 0) {
        int t = wsum[lane];
        #pragma unroll
        for (int d = 16; d > 0; d >>= 1) t += __shfl_down_sync(0xffffffffu, t, d);
        if (lane == 0) g_part[blockIdx.x] = t;
    }
}

__global__ void k_scan_b() {
    __shared__ int w0[2];
    int tid = threadIdx.x;          // 64 threads
    int lane = tid & 31, wid = tid >> 5;
    int v = (tid < SCB) ? g_part[tid] : 0;
    int inc = v;
    #pragma unroll
    for (int d = 1; d < 32; d <<= 1) {
        int t = __shfl_up_sync(0xffffffffu, inc, d);
        if (lane >= d) inc += t;
    }
    if (lane == 31) w0[wid] = inc;
    __syncthreads();
    int off = (wid == 1) ? w0[0] : 0;
    if (tid < SCB) g_part[tid] = off + inc - v;   // exclusive
    if (tid == 63) g_rowptr[NN] = w0[0] + w0[1];
}

__global__ __launch_bounds__(1024) void k_scan_c() {
    __shared__ int winc[32];
    __shared__ int woff[32];
    int i = blockIdx.x * 1024 + threadIdx.x;
    int lane = threadIdx.x & 31, wid = threadIdx.x >> 5;
    int c = (i < NN) ? g_degcnt[i] : 0;
    int inc = c;
    #pragma unroll
    for (int d = 1; d < 32; d <<= 1) {
        int t = __shfl_up_sync(0xffffffffu, inc, d);
        if (lane >= d) inc += t;
    }
    if (lane == 31) winc[wid] = inc;
    __syncthreads();
    if (wid == 0) {
        int v = winc[lane];
        int vi = v;
        #pragma unroll
        for (int d = 1; d < 32; d <<= 1) {
            int t = __shfl_up_sync(0xffffffffu, vi, d);
            if (lane >= d) vi += t;
        }
        woff[lane] = vi - v;
    }
    __syncthreads();
    if (i < NN) {
        int run = g_part[blockIdx.x] + woff[wid] + (inc - c);
        g_rowptr[i] = run;
        g_fill[i]   = run;
        g_invdeg[i] = 1.0f / (float)(c + 1);
    }
}

__global__ void k_fill(const int* __restrict__ ei) {
    int e = blockIdx.x * blockDim.x + threadIdx.x;
    if (e < EE) {
        int r = ei[e];
        int c = ei[EE + e];
        if ((unsigned)r < NN && (unsigned)c < NN) {
            int p = atomicAdd(&g_fill[r], 1);
            if ((unsigned)p < EE) g_col[p] = c;
        }
    }
}

// ---------------------------------------------------------------------------
// Fused dropout-multiply + fp16 convert + GEMM:  z = (x*dm) @ W1
__global__ __launch_bounds__(256) void k_gemm_fused(const float* __restrict__ x,
                                                    const float* __restrict__ dm) {
    __shared__ __align__(16) __half As[64][KC + 8];
    __shared__ __align__(16) __half Bs[KC][HH + 8];
    int tid = threadIdx.x;
    int warp = tid >> 5, lane = tid & 31;
    int wm = warp >> 2;
    int wn = warp & 3;
    int m0 = blockIdx.x * 64;

    wmma::fragment<wmma::accumulator, 16, 16, 16, float> c[2][4];
    #pragma unroll
    for (int i = 0; i < 2; i++)
        #pragma unroll
        for (int j = 0; j < 4; j++) wmma::fill_fragment(c[i][j], 0.f);

    for (int kk = 0; kk < HH; kk += KC) {
        #pragma unroll
        for (int i = 0; i < 2; i++) {
            int idx = tid + i * 256;
            int row = idx >> 3;
            int c4  = (idx & 7) * 4;
            int grow = m0 + row;
            __half2 h0, h1;
            if (grow < NN) {
                float4 xv = *(const float4*)(x  + (size_t)grow * HH + kk + c4);
                float4 dv = *(const float4*)(dm + (size_t)grow * HH + kk + c4);
                h0 = __floats2half2_rn(xv.x*dv.x, xv.y*dv.y);
                h1 = __floats2half2_rn(xv.z*dv.z, xv.w*dv.w);
            } else {
                h0 = __floats2half2_rn(0.f, 0.f);
                h1 = h0;
            }
            *(__half2*)&As[row][c4]     = h0;
            *(__half2*)&As[row][c4 + 2] = h1;
        }
        #pragma unroll
        for (int i = 0; i < 4; i++) {
            int idx = tid + i * 256;
            int row = idx >> 5;
            int c8  = (idx & 31) * 8;
            *(uint4*)&Bs[row][c8] = *(const uint4*)(g_w1h + (size_t)(kk + row) * HH + c8);
        }
        __syncthreads();
        #pragma unroll
        for (int ks = 0; ks < KC; ks += 16) {
            wmma::fragment<wmma::matrix_a, 16, 16, 16, __half, wmma::row_major> a[2];
            #pragma unroll
            for (int i = 0; i < 2; i++)
                wmma::load_matrix_sync(a[i], &As[wm*32 + 16*i][ks], KC + 8);
            #pragma unroll
            for (int j = 0; j < 4; j++) {
                wmma::fragment<wmma::matrix_b, 16, 16, 16, __half, wmma::row_major> b;
                wmma::load_matrix_sync(b, &Bs[ks][wn*64 + 16*j], HH + 8);
                wmma::mma_sync(c[0][j], a[0], b, c[0][j]);
                wmma::mma_sync(c[1][j], a[1], b, c[1][j]);
            }
        }
        __syncthreads();
    }

    float* stg = (float*)Bs + warp * 320;
    #pragma unroll
    for (int i = 0; i < 2; i++)
        #pragma unroll
        for (int j = 0; j < 4; j++) {
            wmma::store_matrix_sync(stg, c[i][j], 20, wmma::mem_row_major);
            __syncwarp();
            if (lane < 16) {
                const float* sr = stg + lane * 20;
                __half2 hh[8];
                #pragma unroll
                for (int p = 0; p < 8; p++)
                    hh[p] = __floats2half2_rn(sr[2*p], sr[2*p+1]);
                int gr = m0 + wm*32 + i*16 + lane;
                __half* dst = g_z + (size_t)gr * HH + wn*64 + j*16;
                ((uint4*)dst)[0] = ((uint4*)hh)[0];
                ((uint4*)dst)[1] = ((uint4*)hh)[1];
            }
            __syncwarp();
        }
}

// ---------------------------------------------------------------------------
__device__ __forceinline__ void load_row8(const __half* base, int lane, float f[8]) {
    uint4 raw = ((const uint4*)base)[lane];
    __half2* h = (__half2*)&raw;
    float2 t;
    t = __half22float2(h[0]); f[0] = t.x; f[1] = t.y;
    t = __half22float2(h[1]); f[2] = t.x; f[3] = t.y;
    t = __half22float2(h[2]); f[4] = t.x; f[5] = t.y;
    t = __half22float2(h[3]); f[6] = t.x; f[7] = t.y;
}
// fold a raw 16B half-row chunk into fp32 accumulators
__device__ __forceinline__ void acc8(float a[8], uint4 raw) {
    __half2* h = (__half2*)&raw;
    float2 t;
    t = __half22float2(h[0]); a[0] += t.x; a[1] += t.y;
    t = __half22float2(h[1]); a[2] += t.x; a[3] += t.y;
    t = __half22float2(h[2]); a[4] += t.x; a[5] += t.y;
    t = __half22float2(h[3]); a[6] += t.x; a[7] += t.y;
}
__device__ __forceinline__ void acc8m(float a[8], uint4 raw, float m) {
    __half2* h = (__half2*)&raw;
    float2 t;
    t = __half22float2(h[0]); a[0] += m*t.x; a[1] += m*t.y;
    t = __half22float2(h[1]); a[2] += m*t.x; a[3] += m*t.y;
    t = __half22float2(h[2]); a[4] += m*t.x; a[5] += m*t.y;
    t = __half22float2(h[3]); a[6] += m*t.x; a[7] += m*t.y;
}
// evict-first store: output rows are not re-read within the pass
__device__ __forceinline__ void store_row8_cs(__half* base, int lane, const float f[8], float scale) {
    __half2 h[4];
    #pragma unroll
    for (int p = 0; p < 4; p++)
        h[p] = __floats2half2_rn(f[2*p] * scale, f[2*p+1] * scale);
    __stcs((uint4*)base + lane, *(uint4*)h);
}

// Fused first propagation step for all 4 views; 2x-unrolled edge loop.
__global__ __launch_bounds__(256) void k_step1() {
    int gw = (blockIdx.x * blockDim.x + threadIdx.x) >> 5;
    int lane = threadIdx.x & 31;
    if (gw >= NN) return;
    int r = gw;

    const uint4* zr = (const uint4*)(g_z + (size_t)r * HH);
    uint4 sr0 = zr[lane];
    float s[8] = {0,0,0,0,0,0,0,0};
    acc8(s, sr0);

    float4 mr = g_mask4[r];
    float mm[VV] = {mr.x, mr.y, mr.z, mr.w};
    float a[VV][8];
    #pragma unroll
    for (int v = 0; v < VV; v++)
        #pragma unroll
        for (int q = 0; q < 8; q++) a[v][q] = s[q] * mm[v];

    int jb = g_rowptr[r], je = g_rowptr[r + 1];
    int j = jb;
    for (; j + 1 < je; j += 2) {
        int c0 = g_col[j], c1 = g_col[j + 1];
        uint4 r0 = ((const uint4*)(g_z + (size_t)c0 * HH))[lane];
        uint4 r1 = ((const uint4*)(g_z + (size_t)c1 * HH))[lane];
        float4 m0 = g_mask4[c0];
        float4 m1 = g_mask4[c1];
        acc8m(a[0], r0, m0.x); acc8m(a[1], r0, m0.y);
        acc8m(a[2], r0, m0.z); acc8m(a[3], r0, m0.w);
        acc8m(a[0], r1, m1.x); acc8m(a[1], r1, m1.y);
        acc8m(a[2], r1, m1.z); acc8m(a[3], r1, m1.w);
    }
    if (j < je) {
        int c = g_col[j];
        uint4 r0 = ((const uint4*)(g_z + (size_t)c * HH))[lane];
        float4 m0 = g_mask4[c];
        acc8m(a[0], r0, m0.x); acc8m(a[1], r0, m0.y);
        acc8m(a[2], r0, m0.z); acc8m(a[3], r0, m0.w);
    }
    float inv = g_invdeg[r];
    #pragma unroll
    for (int v = 0; v < VV; v++)
        store_row8_cs(g_pairs[v >> 1] + (size_t)r * PH + (v & 1) * HH, lane, a[v], inv);
}

// one propagation step for one view-pair; 4x-unrolled edge loop for MLP.
__global__ __launch_bounds__(256) void k_spmm2(int pair, int dir) {
    const __half* in = dir ? g_ptmp[pair] : g_pairs[pair];
    __half* out      = dir ? g_pairs[pair] : g_ptmp[pair];

    int gw = (blockIdx.x * blockDim.x + threadIdx.x) >> 5;
    int lane = threadIdx.x & 31;
    if (gw >= NN) return;
    int r = gw;

    float a0[8], a1[8];
    const __half* srow = in + (size_t)r * PH;
    load_row8(srow,      lane, a0);
    load_row8(srow + HH, lane, a1);

    int jb = g_rowptr[r], je = g_rowptr[r + 1];
    int j = jb;
    for (; j + 3 < je; j += 4) {
        int c0 = g_col[j], c1 = g_col[j+1], c2 = g_col[j+2], c3 = g_col[j+3];
        const uint4* p0 = (const uint4*)(in + (size_t)c0 * PH);
        const uint4* p1 = (const uint4*)(in + (size_t)c1 * PH);
        const uint4* p2 = (const uint4*)(in + (size_t)c2 * PH);
        const uint4* p3 = (const uint4*)(in + (size_t)c3 * PH);
        uint4 r00 = p0[lane], r01 = p0[lane + 32];
        uint4 r10 = p1[lane], r11 = p1[lane + 32];
        uint4 r20 = p2[lane], r21 = p2[lane + 32];
        uint4 r30 = p3[lane], r31 = p3[lane + 32];
        acc8(a0, r00); acc8(a0, r10); acc8(a0, r20); acc8(a0, r30);
        acc8(a1, r01); acc8(a1, r11); acc8(a1, r21); acc8(a1, r31);
    }
    for (; j < je; j++) {
        int c = g_col[j];
        const uint4* p = (const uint4*)(in + (size_t)c * PH);
        uint4 u0 = p[lane], u1 = p[lane + 32];
        acc8(a0, u0);
        acc8(a1, u1);
    }
    float inv = g_invdeg[r];
    __half* orow = out + (size_t)r * PH;
    store_row8_cs(orow,      lane, a0, inv);
    store_row8_cs(orow + HH, lane, a1, inv);
}

// ---------------------------------------------------------------------------
// pooled[v][b][f] += relu(state[r][v][f] + b1[f]) for batch[r]==b
__global__ __launch_bounds__(256) void k_pool(const int* __restrict__ batch,
                                              const float* __restrict__ b1) {
    int v  = blockIdx.y;
    int f  = threadIdx.x;
    int r0 = blockIdx.x * 64;
    const __half* in = g_pairs[v >> 1] + (size_t)(v & 1) * HH;
    float bias = b1[f];
    float acc = 0.f;
    int curb = -1;
    int rend = r0 + 64; if (rend > NN) rend = NN;
    for (int r = r0; r < rend; r++) {
        int b = batch[r];
        if ((unsigned)b >= BB) continue;
        if (b != curb) {
            if (curb >= 0) atomicAdd(&g_pool[(curb + v * BB) * HH + f], acc);
            acc = 0.f; curb = b;
        }
        float val = __half2float(in[(size_t)r * PH + f]) + bias;
        acc += fmaxf(val, 0.f);
    }
    if (curb >= 0) atomicAdd(&g_pool[(curb + v * BB) * HH + f], acc);
}

__global__ __launch_bounds__(256) void k_head(const float* __restrict__ W2,
                                              const float* __restrict__ b2,
                                              const float* __restrict__ Wc,
                                              const float* __restrict__ bcv,
                                              float* __restrict__ out) {
    __shared__ float sp[HH];
    __shared__ float sy[HH];
    __shared__ float slog[CC];
    int vb = blockIdx.x;
    int v = vb >> 7, b = vb & 127;
    int tid = threadIdx.x;

    float cnt = (float)g_counts[b];
    if (cnt < 1.f) cnt = 1.f;
    sp[tid] = g_pool[(v * BB + b) * HH + tid] / cnt;
    __syncthreads();

    float acc = b2[tid];
    #pragma unroll 8
    for (int h = 0; h < HH; h++) acc += sp[h] * W2[h * HH + tid];
    sy[tid] = acc;
    __syncthreads();

    if (tid < CC) {
        float l = bcv[tid];
        #pragma unroll 8
        for (int h = 0; h < HH; h++) l += sy[h] * Wc[h * CC + tid];
        slog[tid] = l;
    }
    __syncthreads();

    if (tid == 0) {
        float mx = -1e30f;
        #pragma unroll
        for (int c = 0; c < CC; c++) mx = fmaxf(mx, slog[c]);
        float s = 0.f, e[CC];
        #pragma unroll
        for (int c = 0; c < CC; c++) { e[c] = expf(slog[c] - mx); s += e[c]; }
        float invs = 1.f / s;
        #pragma unroll
        for (int c = 0; c < CC; c++) g_probs[(v * BB + b) * CC + c] = e[c] * invs;
        if (v == 0) {
            #pragma unroll
            for (int c = 0; c < CC; c++) out[b * CC + c] = slog[c];
        }
    }
}

__global__ void k_loss(float* __restrict__ out, int out_size) {
    __shared__ float sc[BB], se[BB];
    int b = threadIdx.x;
    float mp[CC];
    #pragma unroll
    for (int c = 0; c < CC; c++) {
        float s = 0.f;
        #pragma unroll
        for (int v = 0; v < VV; v++) s += g_probs[(v * BB + b) * CC + c];
        mp[c] = s * (1.0f / VV);
    }
    float cons = 0.f;
    #pragma unroll
    for (int v = 0; v < VV; v++)
        #pragma unroll
        for (int c = 0; c < CC; c++) {
            float d = g_probs[(v * BB + b) * CC + c] - mp[c];
            cons += d * d;
        }
    float ent = 0.f;
    #pragma unroll
    for (int c = 0; c < CC; c++) ent -= mp[c] * logf(mp[c] + 1e-8f);
    sc[b] = cons; se[b] = ent;
    __syncthreads();
    for (int s = 64; s > 0; s >>= 1) {
        if (b < s) { sc[b] += sc[b + s]; se[b] += se[b + s]; }
        __syncthreads();
    }
    if (b == 0)
        out[out_size - 1] = 1.0f * (sc[0] / (float)(VV * BB)) + se[0] / (float)BB;
}

// ---------------------------------------------------------------------------
extern "C" void kernel_launch(void* const* d_in, const int* in_sizes, int n_in,
                              void* d_out, int out_size) {
    const float* x     = (const float*)d_in[0];
    const int*   ei    = (const int*)d_in[1];
    const int*   batch = (const int*)d_in[2];
    const float* dm    = (const float*)d_in[3];
    const float* masks = (const float*)d_in[4];
    const float* W1    = (const float*)d_in[5];
    const float* b1    = (const float*)d_in[6];
    const float* W2    = (const float*)d_in[7];
    const float* b2    = (const float*)d_in[8];
    const float* Wc    = (const float*)d_in[9];
    const float* bcv   = (const float*)d_in[10];
    float* out = (float*)d_out;

    // fork/join: CSR chain on capture stream, GEMM on side stream.
    cudaStream_t s2;
    cudaStreamCreate(&s2);
    cudaEvent_t eFork, eJoin;
    cudaEventCreateWithFlags(&eFork, cudaEventDisableTiming);
    cudaEventCreateWithFlags(&eJoin, cudaEventDisableTiming);

    k_zero<<<(VV*BB*HH + 255) / 256, 256>>>(W1);
    cudaEventRecord(eFork, 0);
    cudaStreamWaitEvent(s2, eFork, 0);

    k_gemm_fused<<<NPAD / 64, 256, 0, s2>>>(x, dm);   // side stream
    cudaEventRecord(eJoin, s2);

    k_hist<<<(EE + 255) / 256, 256>>>(ei, batch, masks);
    k_scan_a<<<SCB, 1024>>>();
    k_scan_b<<<1, 64>>>();
    k_scan_c<<<SCB, 1024>>>();
    k_fill<<<(EE + 255) / 256, 256>>>(ei);

    cudaStreamWaitEvent(0, eJoin, 0);                 // join before step1

    int wgrid = (NN * 32 + 255) / 256;
    k_step1<<<wgrid, 256>>>();
    k_spmm2<<<wgrid, 256>>>(0, 0);   // pair0 step2
    k_spmm2<<<wgrid, 256>>>(0, 1);   // pair0 step3
    k_spmm2<<<wgrid, 256>>>(1, 0);   // pair1 step2
    k_spmm2<<<wgrid, 256>>>(1, 1);   // pair1 step3

    dim3 pgrid((NN + 63) / 64, VV);
    k_pool<<<pgrid, 256>>>(batch, b1);

    k_head<<<VV * BB, 256>>>(W2, b2, Wc, bcv, out);
    k_loss<<<1, BB>>>(out, out_size);
}

// round 12
// speedup vs baseline: 1.0346x; 1.0346x over previous
#include <cuda_runtime.h>
#include <cuda_fp16.h>
#include <mma.h>
using namespace nvcuda;

#define NN 50000
#define NPAD 50048            // 782 * 64, pad for wmma tiles
#define EE 800000
#define HH 256
#define BB 128
#define VV 4
#define CC 10
#define PH 512                // pair row width: 2 views * 256 feats
#define KC 32                 // gemm k-chunk
#define SCB 49                // scan blocks: 49*1024 >= NN

// ---- scratch (device globals; no allocation allowed) ----
__device__ int    g_degcnt[NN];
__device__ int    g_rowptr[NN+1];
__device__ int    g_fill[NN];
__device__ float  g_invdeg[NN];
__device__ int    g_col[EE];
__device__ int    g_counts[BB];
__device__ int    g_part[SCB];              // scan partials
__device__ float4 g_mask4[NN];              // transposed node masks
__device__ __half g_w1h[HH*HH];             // W1 fp16
__device__ __half g_z[NPAD*HH];             // (x*dropout) @ W1, fp16
__device__ __half g_pairs[2][(size_t)NN*PH]; // view pairs {0,1},{2,3}
__device__ __half g_ptmp[2][(size_t)NN*PH];  // ping-pong per pair
__device__ float  g_pool[VV*BB*HH];
__device__ float  g_probs[VV*BB*CC];

// ---------------------------------------------------------------------------
__global__ void k_zero(const float* __restrict__ W1) {
    int i = blockIdx.x * blockDim.x + threadIdx.x;
    if (i < NN) g_degcnt[i] = 0;
    if (i < BB) g_counts[i] = 0;
    if (i < VV*BB*HH) g_pool[i] = 0.f;
    if (i < HH*HH/4) {
        float4 w = *(const float4*)(W1 + i * 4);
        __half2 h[2];
        h[0] = __floats2half2_rn(w.x, w.y);
        h[1] = __floats2half2_rn(w.z, w.w);
        *(uint2*)(g_w1h + i * 4) = *(uint2*)h;
    }
}

// histogram over edge rows + batch counts + mask transpose, one launch
__global__ void k_hist(const int* __restrict__ ei, const int* __restrict__ batch,
                       const float* __restrict__ masks) {
    int e = blockIdx.x * blockDim.x + threadIdx.x;
    if (e < EE) {
        int r = ei[e];
        if ((unsigned)r < NN) atomicAdd(&g_degcnt[r], 1);
    }
    if (e < NN) {
        int b = batch[e];
        if ((unsigned)b < BB) atomicAdd(&g_counts[b], 1);
        g_mask4[e] = make_float4(masks[e], masks[NN + e], masks[2*NN + e], masks[3*NN + e]);
    }
}

// ---- 3-phase grid-wide exclusive scan of g_degcnt -------------------------
__global__ __launch_bounds__(1024) void k_scan_a() {
    __shared__ int wsum[32];
    int i = blockIdx.x * 1024 + threadIdx.x;
    int lane = threadIdx.x & 31, wid = threadIdx.x >> 5;
    int c = (i < NN) ? g_degcnt[i] : 0;
    int s = c;
    #pragma unroll
    for (int d = 16; d > 0; d >>= 1) s += __shfl_down_sync(0xffffffffu, s, d);
    if (lane == 0) wsum[wid] = s;
    __syncthreads();
    if (wid == 0) {
        int t = wsum[lane];
        #pragma unroll
        for (int d = 16; d > 0; d >>= 1) t += __shfl_down_sync(0xffffffffu, t, d);
        if (lane == 0) g_part[blockIdx.x] = t;
    }
}

__global__ void k_scan_b() {
    __shared__ int w0[2];
    int tid = threadIdx.x;          // 64 threads
    int lane = tid & 31, wid = tid >> 5;
    int v = (tid < SCB) ? g_part[tid] : 0;
    int inc = v;
    #pragma unroll
    for (int d = 1; d < 32; d <<= 1) {
        int t = __shfl_up_sync(0xffffffffu, inc, d);
        if (lane >= d) inc += t;
    }
    if (lane == 31) w0[wid] = inc;
    __syncthreads();
    int off = (wid == 1) ? w0[0] : 0;
    if (tid < SCB) g_part[tid] = off + inc - v;   // exclusive
    if (tid == 63) g_rowptr[NN] = w0[0] + w0[1];
}

__global__ __launch_bounds__(1024) void k_scan_c() {
    __shared__ int winc[32];
    __shared__ int woff[32];
    int i = blockIdx.x * 1024 + threadIdx.x;
    int lane = threadIdx.x & 31, wid = threadIdx.x >> 5;
    int c = (i < NN) ? g_degcnt[i] : 0;
    int inc = c;
    #pragma unroll
    for (int d = 1; d < 32; d <<= 1) {
        int t = __shfl_up_sync(0xffffffffu, inc, d);
        if (lane >= d) inc += t;
    }
    if (lane == 31) winc[wid] = inc;
    __syncthreads();
    if (wid == 0) {
        int v = winc[lane];
        int vi = v;
        #pragma unroll
        for (int d = 1; d < 32; d <<= 1) {
            int t = __shfl_up_sync(0xffffffffu, vi, d);
            if (lane >= d) vi += t;
        }
        woff[lane] = vi - v;
    }
    __syncthreads();
    if (i < NN) {
        int run = g_part[blockIdx.x] + woff[wid] + (inc - c);
        g_rowptr[i] = run;
        g_fill[i]   = run;
        g_invdeg[i] = 1.0f / (float)(c + 1);
    }
}

__global__ void k_fill(const int* __restrict__ ei) {
    int e = blockIdx.x * blockDim.x + threadIdx.x;
    if (e < EE) {
        int r = ei[e];
        int c = ei[EE + e];
        if ((unsigned)r < NN && (unsigned)c < NN) {
            int p = atomicAdd(&g_fill[r], 1);
            if ((unsigned)p < EE) g_col[p] = c;
        }
    }
}

// ---------------------------------------------------------------------------
// Fused dropout-multiply + fp16 convert + GEMM:  z = (x*dm) @ W1
__global__ __launch_bounds__(256) void k_gemm_fused(const float* __restrict__ x,
                                                    const float* __restrict__ dm) {
    __shared__ __align__(16) __half As[64][KC + 8];
    __shared__ __align__(16) __half Bs[KC][HH + 8];
    int tid = threadIdx.x;
    int warp = tid >> 5, lane = tid & 31;
    int wm = warp >> 2;
    int wn = warp & 3;
    int m0 = blockIdx.x * 64;

    wmma::fragment<wmma::accumulator, 16, 16, 16, float> c[2][4];
    #pragma unroll
    for (int i = 0; i < 2; i++)
        #pragma unroll
        for (int j = 0; j < 4; j++) wmma::fill_fragment(c[i][j], 0.f);

    for (int kk = 0; kk < HH; kk += KC) {
        #pragma unroll
        for (int i = 0; i < 2; i++) {
            int idx = tid + i * 256;
            int row = idx >> 3;
            int c4  = (idx & 7) * 4;
            int grow = m0 + row;
            __half2 h0, h1;
            if (grow < NN) {
                float4 xv = *(const float4*)(x  + (size_t)grow * HH + kk + c4);
                float4 dv = *(const float4*)(dm + (size_t)grow * HH + kk + c4);
                h0 = __floats2half2_rn(xv.x*dv.x, xv.y*dv.y);
                h1 = __floats2half2_rn(xv.z*dv.z, xv.w*dv.w);
            } else {
                h0 = __floats2half2_rn(0.f, 0.f);
                h1 = h0;
            }
            *(__half2*)&As[row][c4]     = h0;
            *(__half2*)&As[row][c4 + 2] = h1;
        }
        #pragma unroll
        for (int i = 0; i < 4; i++) {
            int idx = tid + i * 256;
            int row = idx >> 5;
            int c8  = (idx & 31) * 8;
            *(uint4*)&Bs[row][c8] = *(const uint4*)(g_w1h + (size_t)(kk + row) * HH + c8);
        }
        __syncthreads();
        #pragma unroll
        for (int ks = 0; ks < KC; ks += 16) {
            wmma::fragment<wmma::matrix_a, 16, 16, 16, __half, wmma::row_major> a[2];
            #pragma unroll
            for (int i = 0; i < 2; i++)
                wmma::load_matrix_sync(a[i], &As[wm*32 + 16*i][ks], KC + 8);
            #pragma unroll
            for (int j = 0; j < 4; j++) {
                wmma::fragment<wmma::matrix_b, 16, 16, 16, __half, wmma::row_major> b;
                wmma::load_matrix_sync(b, &Bs[ks][wn*64 + 16*j], HH + 8);
                wmma::mma_sync(c[0][j], a[0], b, c[0][j]);
                wmma::mma_sync(c[1][j], a[1], b, c[1][j]);
            }
        }
        __syncthreads();
    }

    float* stg = (float*)Bs + warp * 320;
    #pragma unroll
    for (int i = 0; i < 2; i++)
        #pragma unroll
        for (int j = 0; j < 4; j++) {
            wmma::store_matrix_sync(stg, c[i][j], 20, wmma::mem_row_major);
            __syncwarp();
            if (lane < 16) {
                const float* sr = stg + lane * 20;
                __half2 hh[8];
                #pragma unroll
                for (int p = 0; p < 8; p++)
                    hh[p] = __floats2half2_rn(sr[2*p], sr[2*p+1]);
                int gr = m0 + wm*32 + i*16 + lane;
                __half* dst = g_z + (size_t)gr * HH + wn*64 + j*16;
                ((uint4*)dst)[0] = ((uint4*)hh)[0];
                ((uint4*)dst)[1] = ((uint4*)hh)[1];
            }
            __syncwarp();
        }
}

// ---------------------------------------------------------------------------
__device__ __forceinline__ void load_row8(const __half* base, int lane, float f[8]) {
    uint4 raw = ((const uint4*)base)[lane];
    __half2* h = (__half2*)&raw;
    float2 t;
    t = __half22float2(h[0]); f[0] = t.x; f[1] = t.y;
    t = __half22float2(h[1]); f[2] = t.x; f[3] = t.y;
    t = __half22float2(h[2]); f[4] = t.x; f[5] = t.y;
    t = __half22float2(h[3]); f[6] = t.x; f[7] = t.y;
}
// evict-first store: output rows are not re-read within the pass
__device__ __forceinline__ void store_row8_cs(__half* base, int lane, const float f[8], float scale) {
    __half2 h[4];
    #pragma unroll
    for (int p = 0; p < 4; p++)
        h[p] = __floats2half2_rn(f[2*p] * scale, f[2*p+1] * scale);
    __stcs((uint4*)base + lane, *(uint4*)h);
}

// Fused first propagation step for all 4 views; writes pair layouts. (R10 form)
__global__ __launch_bounds__(256) void k_step1() {
    int gw = (blockIdx.x * blockDim.x + threadIdx.x) >> 5;
    int lane = threadIdx.x & 31;
    if (gw >= NN) return;
    int r = gw;

    float s[8];
    load_row8(g_z + (size_t)r * HH, lane, s);

    float4 mr = g_mask4[r];
    float mm[VV] = {mr.x, mr.y, mr.z, mr.w};
    float a[VV][8];
    #pragma unroll
    for (int v = 0; v < VV; v++)
        #pragma unroll
        for (int q = 0; q < 8; q++) a[v][q] = s[q] * mm[v];

    int jb = g_rowptr[r], je = g_rowptr[r + 1];
    for (int j = jb; j < je; j++) {
        int c = g_col[j];
        float cf[8];
        load_row8(g_z + (size_t)c * HH, lane, cf);
        float4 mc = g_mask4[c];
        float mv[VV] = {mc.x, mc.y, mc.z, mc.w};
        #pragma unroll
        for (int v = 0; v < VV; v++)
            #pragma unroll
            for (int q = 0; q < 8; q++) a[v][q] += mv[v] * cf[q];
    }
    float inv = g_invdeg[r];
    #pragma unroll
    for (int v = 0; v < VV; v++)
        store_row8_cs(g_pairs[v >> 1] + (size_t)r * PH + (v & 1) * HH, lane, a[v], inv);
}

// one propagation step for one view-pair; dir=0: pairs->ptmp, dir=1: ptmp->pairs
// (R10 form: 2x-unrolled edge loop)
__global__ __launch_bounds__(256) void k_spmm2(int pair, int dir) {
    const __half* in = dir ? g_ptmp[pair] : g_pairs[pair];
    __half* out      = dir ? g_pairs[pair] : g_ptmp[pair];

    int gw = (blockIdx.x * blockDim.x + threadIdx.x) >> 5;
    int lane = threadIdx.x & 31;
    if (gw >= NN) return;
    int r = gw;

    float a0[8], a1[8];
    const __half* srow = in + (size_t)r * PH;
    load_row8(srow,      lane, a0);
    load_row8(srow + HH, lane, a1);

    int jb = g_rowptr[r], je = g_rowptr[r + 1];
    int j = jb;
    for (; j + 1 < je; j += 2) {
        int c0 = g_col[j], c1 = g_col[j + 1];
        const __half* p0 = in + (size_t)c0 * PH;
        const __half* p1 = in + (size_t)c1 * PH;
        float u0[8], u1[8], w0[8], w1[8];
        load_row8(p0,      lane, u0);
        load_row8(p0 + HH, lane, u1);
        load_row8(p1,      lane, w0);
        load_row8(p1 + HH, lane, w1);
        #pragma unroll
        for (int q = 0; q < 8; q++) { a0[q] += u0[q] + w0[q]; a1[q] += u1[q] + w1[q]; }
    }
    if (j < je) {
        int c = g_col[j];
        const __half* p = in + (size_t)c * PH;
        float u0[8], u1[8];
        load_row8(p,      lane, u0);
        load_row8(p + HH, lane, u1);
        #pragma unroll
        for (int q = 0; q < 8; q++) { a0[q] += u0[q]; a1[q] += u1[q]; }
    }
    float inv = g_invdeg[r];
    __half* orow = out + (size_t)r * PH;
    store_row8_cs(orow,      lane, a0, inv);
    store_row8_cs(orow + HH, lane, a1, inv);
}

// ---------------------------------------------------------------------------
// pooled[v][b][f] += relu(state[r][v][f] + b1[f]) for batch[r]==b
// v = v0 + blockIdx.y : allows pooling a single pair early.
__global__ __launch_bounds__(256) void k_pool(const int* __restrict__ batch,
                                              const float* __restrict__ b1, int v0) {
    int v  = v0 + blockIdx.y;
    int f  = threadIdx.x;
    int r0 = blockIdx.x * 64;
    const __half* in = g_pairs[v >> 1] + (size_t)(v & 1) * HH;
    float bias = b1[f];
    float acc = 0.f;
    int curb = -1;
    int rend = r0 + 64; if (rend > NN) rend = NN;
    for (int r = r0; r < rend; r++) {
        int b = batch[r];
        if ((unsigned)b >= BB) continue;
        if (b != curb) {
            if (curb >= 0) atomicAdd(&g_pool[(curb + v * BB) * HH + f], acc);
            acc = 0.f; curb = b;
        }
        float val = __half2float(in[(size_t)r * PH + f]) + bias;
        acc += fmaxf(val, 0.f);
    }
    if (curb >= 0) atomicAdd(&g_pool[(curb + v * BB) * HH + f], acc);
}

__global__ __launch_bounds__(256) void k_head(const float* __restrict__ W2,
                                              const float* __restrict__ b2,
                                              const float* __restrict__ Wc,
                                              const float* __restrict__ bcv,
                                              float* __restrict__ out) {
    __shared__ float sp[HH];
    __shared__ float sy[HH];
    __shared__ float slog[CC];
    int vb = blockIdx.x;
    int v = vb >> 7, b = vb & 127;
    int tid = threadIdx.x;

    float cnt = (float)g_counts[b];
    if (cnt < 1.f) cnt = 1.f;
    sp[tid] = g_pool[(v * BB + b) * HH + tid] / cnt;
    __syncthreads();

    float acc = b2[tid];
    #pragma unroll 8
    for (int h = 0; h < HH; h++) acc += sp[h] * W2[h * HH + tid];
    sy[tid] = acc;
    __syncthreads();

    if (tid < CC) {
        float l = bcv[tid];
        #pragma unroll 8
        for (int h = 0; h < HH; h++) l += sy[h] * Wc[h * CC + tid];
        slog[tid] = l;
    }
    __syncthreads();

    if (tid == 0) {
        float mx = -1e30f;
        #pragma unroll
        for (int c = 0; c < CC; c++) mx = fmaxf(mx, slog[c]);
        float s = 0.f, e[CC];
        #pragma unroll
        for (int c = 0; c < CC; c++) { e[c] = expf(slog[c] - mx); s += e[c]; }
        float invs = 1.f / s;
        #pragma unroll
        for (int c = 0; c < CC; c++) g_probs[(v * BB + b) * CC + c] = e[c] * invs;
        if (v == 0) {
            #pragma unroll
            for (int c = 0; c < CC; c++) out[b * CC + c] = slog[c];
        }
    }
}

__global__ void k_loss(float* __restrict__ out, int out_size) {
    __shared__ float sc[BB], se[BB];
    int b = threadIdx.x;
    float mp[CC];
    #pragma unroll
    for (int c = 0; c < CC; c++) {
        float s = 0.f;
        #pragma unroll
        for (int v = 0; v < VV; v++) s += g_probs[(v * BB + b) * CC + c];
        mp[c] = s * (1.0f / VV);
    }
    float cons = 0.f;
    #pragma unroll
    for (int v = 0; v < VV; v++)
        #pragma unroll
        for (int c = 0; c < CC; c++) {
            float d = g_probs[(v * BB + b) * CC + c] - mp[c];
            cons += d * d;
        }
    float ent = 0.f;
    #pragma unroll
    for (int c = 0; c < CC; c++) ent -= mp[c] * logf(mp[c] + 1e-8f);
    sc[b] = cons; se[b] = ent;
    __syncthreads();
    for (int s = 64; s > 0; s >>= 1) {
        if (b < s) { sc[b] += sc[b + s]; se[b] += se[b + s]; }
        __syncthreads();
    }
    if (b == 0)
        out[out_size - 1] = 1.0f * (sc[0] / (float)(VV * BB)) + se[0] / (float)BB;
}

// ---------------------------------------------------------------------------
extern "C" void kernel_launch(void* const* d_in, const int* in_sizes, int n_in,
                              void* d_out, int out_size) {
    const float* x     = (const float*)d_in[0];
    const int*   ei    = (const int*)d_in[1];
    const int*   batch = (const int*)d_in[2];
    const float* dm    = (const float*)d_in[3];
    const float* masks = (const float*)d_in[4];
    const float* W1    = (const float*)d_in[5];
    const float* b1    = (const float*)d_in[6];
    const float* W2    = (const float*)d_in[7];
    const float* b2    = (const float*)d_in[8];
    const float* Wc    = (const float*)d_in[9];
    const float* bcv   = (const float*)d_in[10];
    float* out = (float*)d_out;

    // fork/join streams & events (host objects only; graph-capture-legal).
    cudaStream_t s2;
    cudaStreamCreate(&s2);
    cudaEvent_t eFork, eJoin, eP0, eP01;
    cudaEventCreateWithFlags(&eFork, cudaEventDisableTiming);
    cudaEventCreateWithFlags(&eJoin, cudaEventDisableTiming);
    cudaEventCreateWithFlags(&eP0,   cudaEventDisableTiming);
    cudaEventCreateWithFlags(&eP01,  cudaEventDisableTiming);

    k_zero<<<(VV*BB*HH + 255) / 256, 256>>>(W1);
    cudaEventRecord(eFork, 0);
    cudaStreamWaitEvent(s2, eFork, 0);

    k_gemm_fused<<<NPAD / 64, 256, 0, s2>>>(x, dm);   // side stream
    cudaEventRecord(eJoin, s2);

    k_hist<<<(EE + 255) / 256, 256>>>(ei, batch, masks);
    k_scan_a<<<SCB, 1024>>>();
    k_scan_b<<<1, 64>>>();
    k_scan_c<<<SCB, 1024>>>();
    k_fill<<<(EE + 255) / 256, 256>>>(ei);

    cudaStreamWaitEvent(0, eJoin, 0);                 // join before step1

    int wgrid = (NN * 32 + 255) / 256;
    dim3 pgrid((NN + 63) / 64, 2);                    // 2 views per pool launch

    k_step1<<<wgrid, 256>>>();
    k_spmm2<<<wgrid, 256>>>(0, 0);   // pair0 step2
    k_spmm2<<<wgrid, 256>>>(0, 1);   // pair0 step3

    // fork: pool views {0,1} on side stream while pair1 propagates
    cudaEventRecord(eP0, 0);
    cudaStreamWaitEvent(s2, eP0, 0);
    k_pool<<<pgrid, 256, 0, s2>>>(batch, b1, 0);
    cudaEventRecord(eP01, s2);

    k_spmm2<<<wgrid, 256>>>(1, 0);   // pair1 step2
    k_spmm2<<<wgrid, 256>>>(1, 1);   // pair1 step3
    k_pool<<<pgrid, 256>>>(batch, b1, 2);   // views {2,3}

    cudaStreamWaitEvent(0, eP01, 0);                  // join pool01 before head

    k_head<<<VV * BB, 256>>>(W2, b2, Wc, bcv, out);
    k_loss<<<1, BB>>>(out, out_size);
}

// round 13
// speedup vs baseline: 1.0968x; 1.0601x over previous
#include <cuda_runtime.h>
#include <cuda_fp16.h>
#include <mma.h>
using namespace nvcuda;

#define NN 50000
#define NPAD 50048            // 782 * 64, pad for wmma tiles
#define EE 800000
#define HH 256
#define BB 128
#define VV 4
#define CC 10
#define PH 512                // pair row width: 2 views * 256 feats
#define KC 32                 // gemm k-chunk
#define SCB 49                // scan blocks: 49*1024 >= NN

// ---- scratch (device globals; no allocation allowed) ----
__device__ int    g_degcnt[NN];
__device__ int    g_rowptr[NN+1];
__device__ int    g_fill[NN];
__device__ float  g_invdeg[NN];
__device__ int    g_col[EE];
__device__ int    g_counts[BB];
__device__ int    g_part[SCB];              // scan partials
__device__ uint2  g_mask4h[NN];             // node masks as 4 x half (exactly 0/1)
__device__ __half g_w1h[HH*HH];             // W1 fp16
__device__ __half g_z[NPAD*HH];             // (x*dropout) @ W1, fp16
__device__ __half g_pairs[2][(size_t)NN*PH]; // view pairs {0,1},{2,3}
__device__ __half g_ptmp[2][(size_t)NN*PH];  // ping-pong per pair
__device__ float  g_pool[VV*BB*HH];
__device__ float  g_probs[VV*BB*CC];

// ---------------------------------------------------------------------------
__global__ void k_zero(const float* __restrict__ W1) {
    int i = blockIdx.x * blockDim.x + threadIdx.x;
    if (i < NN) g_degcnt[i] = 0;
    if (i < BB) g_counts[i] = 0;
    if (i < VV*BB*HH) g_pool[i] = 0.f;
    if (i < HH*HH/4) {
        float4 w = *(const float4*)(W1 + i * 4);
        __half2 h[2];
        h[0] = __floats2half2_rn(w.x, w.y);
        h[1] = __floats2half2_rn(w.z, w.w);
        *(uint2*)(g_w1h + i * 4) = *(uint2*)h;
    }
}

// histogram over edge rows + batch counts + mask transpose (to half4), one launch
__global__ void k_hist(const int* __restrict__ ei, const int* __restrict__ batch,
                       const float* __restrict__ masks) {
    int e = blockIdx.x * blockDim.x + threadIdx.x;
    if (e < EE) {
        int r = ei[e];
        if ((unsigned)r < NN) atomicAdd(&g_degcnt[r], 1);
    }
    if (e < NN) {
        int b = batch[e];
        if ((unsigned)b < BB) atomicAdd(&g_counts[b], 1);
        __half2 p01 = __floats2half2_rn(masks[e],        masks[NN + e]);
        __half2 p23 = __floats2half2_rn(masks[2*NN + e], masks[3*NN + e]);
        uint2 u;
        *(__half2*)&u.x = p01;
        *(__half2*)&u.y = p23;
        g_mask4h[e] = u;
    }
}

// ---- 3-phase grid-wide exclusive scan of g_degcnt -------------------------
__global__ __launch_bounds__(1024) void k_scan_a() {
    __shared__ int wsum[32];
    int i = blockIdx.x * 1024 + threadIdx.x;
    int lane = threadIdx.x & 31, wid = threadIdx.x >> 5;
    int c = (i < NN) ? g_degcnt[i] : 0;
    int s = c;
    #pragma unroll
    for (int d = 16; d > 0; d >>= 1) s += __shfl_down_sync(0xffffffffu, s, d);
    if (lane == 0) wsum[wid] = s;
    __syncthreads();
    if (wid == 0) {
        int t = wsum[lane];
        #pragma unroll
        for (int d = 16; d > 0; d >>= 1) t += __shfl_down_sync(0xffffffffu, t, d);
        if (lane == 0) g_part[blockIdx.x] = t;
    }
}

__global__ void k_scan_b() {
    __shared__ int w0[2];
    int tid = threadIdx.x;          // 64 threads
    int lane = tid & 31, wid = tid >> 5;
    int v = (tid < SCB) ? g_part[tid] : 0;
    int inc = v;
    #pragma unroll
    for (int d = 1; d < 32; d <<= 1) {
        int t = __shfl_up_sync(0xffffffffu, inc, d);
        if (lane >= d) inc += t;
    }
    if (lane == 31) w0[wid] = inc;
    __syncthreads();
    int off = (wid == 1) ? w0[0] : 0;
    if (tid < SCB) g_part[tid] = off + inc - v;   // exclusive
    if (tid == 63) g_rowptr[NN] = w0[0] + w0[1];
}

__global__ __launch_bounds__(1024) void k_scan_c() {
    __shared__ int winc[32];
    __shared__ int woff[32];
    int i = blockIdx.x * 1024 + threadIdx.x;
    int lane = threadIdx.x & 31, wid = threadIdx.x >> 5;
    int c = (i < NN) ? g_degcnt[i] : 0;
    int inc = c;
    #pragma unroll
    for (int d = 1; d < 32; d <<= 1) {
        int t = __shfl_up_sync(0xffffffffu, inc, d);
        if (lane >= d) inc += t;
    }
    if (lane == 31) winc[wid] = inc;
    __syncthreads();
    if (wid == 0) {
        int v = winc[lane];
        int vi = v;
        #pragma unroll
        for (int d = 1; d < 32; d <<= 1) {
            int t = __shfl_up_sync(0xffffffffu, vi, d);
            if (lane >= d) vi += t;
        }
        woff[lane] = vi - v;
    }
    __syncthreads();
    if (i < NN) {
        int run = g_part[blockIdx.x] + woff[wid] + (inc - c);
        g_rowptr[i] = run;
        g_fill[i]   = run;
        g_invdeg[i] = 1.0f / (float)(c + 1);
    }
}

__global__ void k_fill(const int* __restrict__ ei) {
    int e = blockIdx.x * blockDim.x + threadIdx.x;
    if (e < EE) {
        int r = ei[e];
        int c = ei[EE + e];
        if ((unsigned)r < NN && (unsigned)c < NN) {
            int p = atomicAdd(&g_fill[r], 1);
            if ((unsigned)p < EE) g_col[p] = c;
        }
    }
}

// ---------------------------------------------------------------------------
// Fused dropout-multiply + fp16 convert + GEMM:  z = (x*dm) @ W1
__global__ __launch_bounds__(256) void k_gemm_fused(const float* __restrict__ x,
                                                    const float* __restrict__ dm) {
    __shared__ __align__(16) __half As[64][KC + 8];
    __shared__ __align__(16) __half Bs[KC][HH + 8];
    int tid = threadIdx.x;
    int warp = tid >> 5, lane = tid & 31;
    int wm = warp >> 2;
    int wn = warp & 3;
    int m0 = blockIdx.x * 64;

    wmma::fragment<wmma::accumulator, 16, 16, 16, float> c[2][4];
    #pragma unroll
    for (int i = 0; i < 2; i++)
        #pragma unroll
        for (int j = 0; j < 4; j++) wmma::fill_fragment(c[i][j], 0.f);

    for (int kk = 0; kk < HH; kk += KC) {
        #pragma unroll
        for (int i = 0; i < 2; i++) {
            int idx = tid + i * 256;
            int row = idx >> 3;
            int c4  = (idx & 7) * 4;
            int grow = m0 + row;
            __half2 h0, h1;
            if (grow < NN) {
                float4 xv = *(const float4*)(x  + (size_t)grow * HH + kk + c4);
                float4 dv = *(const float4*)(dm + (size_t)grow * HH + kk + c4);
                h0 = __floats2half2_rn(xv.x*dv.x, xv.y*dv.y);
                h1 = __floats2half2_rn(xv.z*dv.z, xv.w*dv.w);
            } else {
                h0 = __floats2half2_rn(0.f, 0.f);
                h1 = h0;
            }
            *(__half2*)&As[row][c4]     = h0;
            *(__half2*)&As[row][c4 + 2] = h1;
        }
        #pragma unroll
        for (int i = 0; i < 4; i++) {
            int idx = tid + i * 256;
            int row = idx >> 5;
            int c8  = (idx & 31) * 8;
            *(uint4*)&Bs[row][c8] = *(const uint4*)(g_w1h + (size_t)(kk + row) * HH + c8);
        }
        __syncthreads();
        #pragma unroll
        for (int ks = 0; ks < KC; ks += 16) {
            wmma::fragment<wmma::matrix_a, 16, 16, 16, __half, wmma::row_major> a[2];
            #pragma unroll
            for (int i = 0; i < 2; i++)
                wmma::load_matrix_sync(a[i], &As[wm*32 + 16*i][ks], KC + 8);
            #pragma unroll
            for (int j = 0; j < 4; j++) {
                wmma::fragment<wmma::matrix_b, 16, 16, 16, __half, wmma::row_major> b;
                wmma::load_matrix_sync(b, &Bs[ks][wn*64 + 16*j], HH + 8);
                wmma::mma_sync(c[0][j], a[0], b, c[0][j]);
                wmma::mma_sync(c[1][j], a[1], b, c[1][j]);
            }
        }
        __syncthreads();
    }

    float* stg = (float*)Bs + warp * 320;
    #pragma unroll
    for (int i = 0; i < 2; i++)
        #pragma unroll
        for (int j = 0; j < 4; j++) {
            wmma::store_matrix_sync(stg, c[i][j], 20, wmma::mem_row_major);
            __syncwarp();
            if (lane < 16) {
                const float* sr = stg + lane * 20;
                __half2 hh[8];
                #pragma unroll
                for (int p = 0; p < 8; p++)
                    hh[p] = __floats2half2_rn(sr[2*p], sr[2*p+1]);
                int gr = m0 + wm*32 + i*16 + lane;
                __half* dst = g_z + (size_t)gr * HH + wn*64 + j*16;
                ((uint4*)dst)[0] = ((uint4*)hh)[0];
                ((uint4*)dst)[1] = ((uint4*)hh)[1];
            }
            __syncwarp();
        }
}

// ---------------------------------------------------------------------------
// half2 accumulate helpers (issue-lean SpMM math)
__device__ __forceinline__ void hacc4(__half2 a[4], uint4 raw) {
    __half2* h = (__half2*)&raw;
    a[0] = __hadd2(a[0], h[0]);
    a[1] = __hadd2(a[1], h[1]);
    a[2] = __hadd2(a[2], h[2]);
    a[3] = __hadd2(a[3], h[3]);
}
__device__ __forceinline__ void hfma4(__half2 a[4], uint4 raw, __half2 m) {
    __half2* h = (__half2*)&raw;
    a[0] = __hfma2(h[0], m, a[0]);
    a[1] = __hfma2(h[1], m, a[1]);
    a[2] = __hfma2(h[2], m, a[2]);
    a[3] = __hfma2(h[3], m, a[3]);
}
// scale (fp32) + evict-first store of 4 half2
__device__ __forceinline__ void store_h2x4_cs(__half* base, int lane, const __half2 a[4], float inv) {
    __half2 h[4];
    #pragma unroll
    for (int p = 0; p < 4; p++) {
        float2 f = __half22float2(a[p]);
        h[p] = __floats2half2_rn(f.x * inv, f.y * inv);
    }
    __stcs((uint4*)base + lane, *(uint4*)h);
}

// Fused first propagation step for all 4 views; HFMA2 (masks are exactly 0/1).
__global__ __launch_bounds__(256) void k_step1() {
    int gw = (blockIdx.x * blockDim.x + threadIdx.x) >> 5;
    int lane = threadIdx.x & 31;
    if (gw >= NN) return;
    int r = gw;

    uint4 sz = ((const uint4*)(g_z + (size_t)r * HH))[lane];
    __half2* szh = (__half2*)&sz;

    uint2 mr = g_mask4h[r];
    const __half* mrh = (const __half*)&mr;

    __half2 a[VV][4];
    #pragma unroll
    for (int v = 0; v < VV; v++) {
        __half2 mh = __half2half2(mrh[v]);
        #pragma unroll
        for (int k = 0; k < 4; k++) a[v][k] = __hmul2(szh[k], mh);
    }

    int jb = g_rowptr[r], je = g_rowptr[r + 1];
    int j = jb;
    for (; j + 1 < je; j += 2) {
        int c0 = g_col[j], c1 = g_col[j + 1];
        uint4 z0 = ((const uint4*)(g_z + (size_t)c0 * HH))[lane];
        uint4 z1 = ((const uint4*)(g_z + (size_t)c1 * HH))[lane];
        uint2 m0 = g_mask4h[c0];
        uint2 m1 = g_mask4h[c1];
        const __half* m0h = (const __half*)&m0;
        const __half* m1h = (const __half*)&m1;
        #pragma unroll
        for (int v = 0; v < VV; v++) {
            hfma4(a[v], z0, __half2half2(m0h[v]));
            hfma4(a[v], z1, __half2half2(m1h[v]));
        }
    }
    if (j < je) {
        int c = g_col[j];
        uint4 z0 = ((const uint4*)(g_z + (size_t)c * HH))[lane];
        uint2 m0 = g_mask4h[c];
        const __half* m0h = (const __half*)&m0;
        #pragma unroll
        for (int v = 0; v < VV; v++)
            hfma4(a[v], z0, __half2half2(m0h[v]));
    }
    float inv = g_invdeg[r];
    #pragma unroll
    for (int v = 0; v < VV; v++)
        store_h2x4_cs(g_pairs[v >> 1] + (size_t)r * PH + (v & 1) * HH, lane, a[v], inv);
}

// one propagation step for one view-pair; HADD2 accumulation.
__global__ __launch_bounds__(256) void k_spmm2(int pair, int dir) {
    const __half* in = dir ? g_ptmp[pair] : g_pairs[pair];
    __half* out      = dir ? g_pairs[pair] : g_ptmp[pair];

    int gw = (blockIdx.x * blockDim.x + threadIdx.x) >> 5;
    int lane = threadIdx.x & 31;
    if (gw >= NN) return;
    int r = gw;

    const uint4* sp = (const uint4*)(in + (size_t)r * PH);
    uint4 s0 = sp[lane], s1 = sp[lane + 32];
    __half2 a0[4], a1[4];
    *(uint4*)a0 = s0;
    *(uint4*)a1 = s1;

    int jb = g_rowptr[r], je = g_rowptr[r + 1];
    int j = jb;
    for (; j + 1 < je; j += 2) {
        int c0 = g_col[j], c1 = g_col[j + 1];
        const uint4* p0 = (const uint4*)(in + (size_t)c0 * PH);
        const uint4* p1 = (const uint4*)(in + (size_t)c1 * PH);
        uint4 r00 = p0[lane], r01 = p0[lane + 32];
        uint4 r10 = p1[lane], r11 = p1[lane + 32];
        hacc4(a0, r00); hacc4(a1, r01);
        hacc4(a0, r10); hacc4(a1, r11);
    }
    if (j < je) {
        int c = g_col[j];
        const uint4* p = (const uint4*)(in + (size_t)c * PH);
        uint4 u0 = p[lane], u1 = p[lane + 32];
        hacc4(a0, u0);
        hacc4(a1, u1);
    }
    float inv = g_invdeg[r];
    __half* orow = out + (size_t)r * PH;
    store_h2x4_cs(orow,      lane, a0, inv);
    store_h2x4_cs(orow + HH, lane, a1, inv);
}

// ---------------------------------------------------------------------------
// pooled[v][b][f] += relu(state[r][v][f] + b1[f]) for batch[r]==b
__global__ __launch_bounds__(256) void k_pool(const int* __restrict__ batch,
                                              const float* __restrict__ b1, int v0) {
    int v  = v0 + blockIdx.y;
    int f  = threadIdx.x;
    int r0 = blockIdx.x * 64;
    const __half* in = g_pairs[v >> 1] + (size_t)(v & 1) * HH;
    float bias = b1[f];
    float acc = 0.f;
    int curb = -1;
    int rend = r0 + 64; if (rend > NN) rend = NN;
    for (int r = r0; r < rend; r++) {
        int b = batch[r];
        if ((unsigned)b >= BB) continue;
        if (b != curb) {
            if (curb >= 0) atomicAdd(&g_pool[(curb + v * BB) * HH + f], acc);
            acc = 0.f; curb = b;
        }
        float val = __half2float(in[(size_t)r * PH + f]) + bias;
        acc += fmaxf(val, 0.f);
    }
    if (curb >= 0) atomicAdd(&g_pool[(curb + v * BB) * HH + f], acc);
}

__global__ __launch_bounds__(256) void k_head(const float* __restrict__ W2,
                                              const float* __restrict__ b2,
                                              const float* __restrict__ Wc,
                                              const float* __restrict__ bcv,
                                              float* __restrict__ out) {
    __shared__ float sp[HH];
    __shared__ float sy[HH];
    __shared__ float slog[CC];
    int vb = blockIdx.x;
    int v = vb >> 7, b = vb & 127;
    int tid = threadIdx.x;

    float cnt = (float)g_counts[b];
    if (cnt < 1.f) cnt = 1.f;
    sp[tid] = g_pool[(v * BB + b) * HH + tid] / cnt;
    __syncthreads();

    float acc = b2[tid];
    #pragma unroll 8
    for (int h = 0; h < HH; h++) acc += sp[h] * W2[h * HH + tid];
    sy[tid] = acc;
    __syncthreads();

    if (tid < CC) {
        float l = bcv[tid];
        #pragma unroll 8
        for (int h = 0; h < HH; h++) l += sy[h] * Wc[h * CC + tid];
        slog[tid] = l;
    }
    __syncthreads();

    if (tid == 0) {
        float mx = -1e30f;
        #pragma unroll
        for (int c = 0; c < CC; c++) mx = fmaxf(mx, slog[c]);
        float s = 0.f, e[CC];
        #pragma unroll
        for (int c = 0; c < CC; c++) { e[c] = expf(slog[c] - mx); s += e[c]; }
        float invs = 1.f / s;
        #pragma unroll
        for (int c = 0; c < CC; c++) g_probs[(v * BB + b) * CC + c] = e[c] * invs;
        if (v == 0) {
            #pragma unroll
            for (int c = 0; c < CC; c++) out[b * CC + c] = slog[c];
        }
    }
}

__global__ void k_loss(float* __restrict__ out, int out_size) {
    __shared__ float sc[BB], se[BB];
    int b = threadIdx.x;
    float mp[CC];
    #pragma unroll
    for (int c = 0; c < CC; c++) {
        float s = 0.f;
        #pragma unroll
        for (int v = 0; v < VV; v++) s += g_probs[(v * BB + b) * CC + c];
        mp[c] = s * (1.0f / VV);
    }
    float cons = 0.f;
    #pragma unroll
    for (int v = 0; v < VV; v++)
        #pragma unroll
        for (int c = 0; c < CC; c++) {
            float d = g_probs[(v * BB + b) * CC + c] - mp[c];
            cons += d * d;
        }
    float ent = 0.f;
    #pragma unroll
    for (int c = 0; c < CC; c++) ent -= mp[c] * logf(mp[c] + 1e-8f);
    sc[b] = cons; se[b] = ent;
    __syncthreads();
    for (int s = 64; s > 0; s >>= 1) {
        if (b < s) { sc[b] += sc[b + s]; se[b] += se[b + s]; }
        __syncthreads();
    }
    if (b == 0)
        out[out_size - 1] = 1.0f * (sc[0] / (float)(VV * BB)) + se[0] / (float)BB;
}

// ---------------------------------------------------------------------------
extern "C" void kernel_launch(void* const* d_in, const int* in_sizes, int n_in,
                              void* d_out, int out_size) {
    const float* x     = (const float*)d_in[0];
    const int*   ei    = (const int*)d_in[1];
    const int*   batch = (const int*)d_in[2];
    const float* dm    = (const float*)d_in[3];
    const float* masks = (const float*)d_in[4];
    const float* W1    = (const float*)d_in[5];
    const float* b1    = (const float*)d_in[6];
    const float* W2    = (const float*)d_in[7];
    const float* b2    = (const float*)d_in[8];
    const float* Wc    = (const float*)d_in[9];
    const float* bcv   = (const float*)d_in[10];
    float* out = (float*)d_out;

    // fork/join streams & events (host objects only; graph-capture-legal).
    cudaStream_t s2;
    cudaStreamCreate(&s2);
    cudaEvent_t eFork, eJoin, eP0, eP01;
    cudaEventCreateWithFlags(&eFork, cudaEventDisableTiming);
    cudaEventCreateWithFlags(&eJoin, cudaEventDisableTiming);
    cudaEventCreateWithFlags(&eP0,   cudaEventDisableTiming);
    cudaEventCreateWithFlags(&eP01,  cudaEventDisableTiming);

    k_zero<<<(VV*BB*HH + 255) / 256, 256>>>(W1);
    cudaEventRecord(eFork, 0);
    cudaStreamWaitEvent(s2, eFork, 0);

    k_gemm_fused<<<NPAD / 64, 256, 0, s2>>>(x, dm);   // side stream
    cudaEventRecord(eJoin, s2);

    k_hist<<<(EE + 255) / 256, 256>>>(ei, batch, masks);
    k_scan_a<<<SCB, 1024>>>();
    k_scan_b<<<1, 64>>>();
    k_scan_c<<<SCB, 1024>>>();
    k_fill<<<(EE + 255) / 256, 256>>>(ei);

    cudaStreamWaitEvent(0, eJoin, 0);                 // join before step1

    int wgrid = (NN * 32 + 255) / 256;
    dim3 pgrid((NN + 63) / 64, 2);                    // 2 views per pool launch

    k_step1<<<wgrid, 256>>>();
    k_spmm2<<<wgrid, 256>>>(0, 0);   // pair0 step2
    k_spmm2<<<wgrid, 256>>>(0, 1);   // pair0 step3

    // fork: pool views {0,1} on side stream while pair1 propagates
    cudaEventRecord(eP0, 0);
    cudaStreamWaitEvent(s2, eP0, 0);
    k_pool<<<pgrid, 256, 0, s2>>>(batch, b1, 0);
    cudaEventRecord(eP01, s2);

    k_spmm2<<<wgrid, 256>>>(1, 0);   // pair1 step2
    k_spmm2<<<wgrid, 256>>>(1, 1);   // pair1 step3
    k_pool<<<pgrid, 256>>>(batch, b1, 2);   // views {2,3}

    cudaStreamWaitEvent(0, eP01, 0);                  // join pool01 before head

    k_head<<<VV * BB, 256>>>(W2, b2, Wc, bcv, out);
    k_loss<<<1, BB>>>(out, out_size);
}

// round 14
// speedup vs baseline: 1.1073x; 1.0096x over previous
#include <cuda_runtime.h>
#include <cuda_fp16.h>
#include <mma.h>
using namespace nvcuda;

#define NN 50000
#define NPAD 50048            // 782 * 64, pad for wmma tiles
#define EE 800000
#define HH 256
#define BB 128
#define VV 4
#define CC 10
#define PH 512                // pair row width: 2 views * 256 feats
#define KC 32                 // gemm k-chunk
#define SCB 49                // scan blocks: 49*1024 >= NN

// ---- scratch (device globals; no allocation allowed) ----
__device__ int    g_degcnt[NN];
__device__ int    g_rowptr[NN+1];
__device__ int    g_fill[NN];
__device__ float  g_invdeg[NN];
__device__ int    g_col[EE];
__device__ int    g_counts[BB];
__device__ int    g_part[SCB];              // scan partials (raw block sums)
__device__ uint2  g_mask4h[NN];             // node masks as 4 x half (exactly 0/1)
__device__ __half g_w1h[HH*HH];             // W1 fp16
__device__ __half g_z[NPAD*HH];             // (x*dropout) @ W1, fp16
__device__ __half g_pairs[2][(size_t)NN*PH]; // view pairs {0,1},{2,3}
__device__ __half g_ptmp[2][(size_t)NN*PH];  // ping-pong per pair
__device__ float  g_pool[VV*BB*HH];
__device__ float  g_probs[VV*BB*CC];

// ---------------------------------------------------------------------------
// main-stream zero: only what the CSR chain needs
__global__ void k_zero_main() {
    int i = blockIdx.x * blockDim.x + threadIdx.x;
    if (i < NN) g_degcnt[i] = 0;
    if (i < BB) g_counts[i] = 0;
}

// side-stream zero: pool + W1 fp16 convert (feeds gemm on same stream)
__global__ void k_zero_aux(const float* __restrict__ W1) {
    int i = blockIdx.x * blockDim.x + threadIdx.x;
    if (i < VV*BB*HH) g_pool[i] = 0.f;
    if (i < HH*HH/4) {
        float4 w = *(const float4*)(W1 + i * 4);
        __half2 h[2];
        h[0] = __floats2half2_rn(w.x, w.y);
        h[1] = __floats2half2_rn(w.z, w.w);
        *(uint2*)(g_w1h + i * 4) = *(uint2*)h;
    }
}

// histogram over edge rows (2 edges/thread) + batch counts + mask transpose
__global__ void k_hist(const int* __restrict__ ei, const int* __restrict__ batch,
                       const float* __restrict__ masks) {
    int t = blockIdx.x * blockDim.x + threadIdx.x;
    int e = t * 2;
    if (e + 1 < EE) {
        int r0 = ei[e], r1 = ei[e + 1];
        if ((unsigned)r0 < NN) atomicAdd(&g_degcnt[r0], 1);
        if ((unsigned)r1 < NN) atomicAdd(&g_degcnt[r1], 1);
    } else if (e < EE) {
        int r0 = ei[e];
        if ((unsigned)r0 < NN) atomicAdd(&g_degcnt[r0], 1);
    }
    if (t < NN) {
        int b = batch[t];
        if ((unsigned)b < BB) atomicAdd(&g_counts[b], 1);
        __half2 p01 = __floats2half2_rn(masks[t],        masks[NN + t]);
        __half2 p23 = __floats2half2_rn(masks[2*NN + t], masks[3*NN + t]);
        uint2 u;
        *(__half2*)&u.x = p01;
        *(__half2*)&u.y = p23;
        g_mask4h[t] = u;
    }
}

// ---- 2-phase grid-wide exclusive scan of g_degcnt -------------------------
// phase a: per-block sums
__global__ __launch_bounds__(1024) void k_scan_a() {
    __shared__ int wsum[32];
    int i = blockIdx.x * 1024 + threadIdx.x;
    int lane = threadIdx.x & 31, wid = threadIdx.x >> 5;
    int c = (i < NN) ? g_degcnt[i] : 0;
    int s = c;
    #pragma unroll
    for (int d = 16; d > 0; d >>= 1) s += __shfl_down_sync(0xffffffffu, s, d);
    if (lane == 0) wsum[wid] = s;
    __syncthreads();
    if (wid == 0) {
        int t = wsum[lane];
        #pragma unroll
        for (int d = 16; d > 0; d >>= 1) t += __shfl_down_sync(0xffffffffu, t, d);
        if (lane == 0) g_part[blockIdx.x] = t;
    }
}

// phase c: each block redundantly scans the 49 partials (threads 0-63), then
// block-exclusive scan + offset -> rowptr/fill/invdeg. (k_scan_b folded in.)
__global__ __launch_bounds__(1024) void k_scan_c() {
    __shared__ int winc[32];
    __shared__ int woff[32];
    __shared__ int sexcl[64];
    __shared__ int stotal;
    int tid = threadIdx.x;
    int lane = tid & 31, wid = tid >> 5;

    // -- partial scan (threads 0..63, two warps) --
    if (tid < 64) {
        int v = (tid < SCB) ? g_part[tid] : 0;
        int inc = v;
        #pragma unroll
        for (int d = 1; d < 32; d <<= 1) {
            int t = __shfl_up_sync(0xffffffffu, inc, d);
            if (lane >= d) inc += t;
        }
        if (lane == 31) winc[wid] = inc;   // reuse winc[0..1] pre-sync
    }
    __syncthreads();
    if (tid < 64) {
        int v = (tid < SCB) ? g_part[tid] : 0;
        int inc = v;
        #pragma unroll
        for (int d = 1; d < 32; d <<= 1) {
            int t = __shfl_up_sync(0xffffffffu, inc, d);
            if (lane >= d) inc += t;
        }
        int off = (wid == 1) ? winc[0] : 0;
        sexcl[tid] = off + inc - v;
        if (tid == 63) stotal = winc[0] + winc[1];
    }
    __syncthreads();

    // -- per-element scan --
    int i = blockIdx.x * 1024 + tid;
    int c = (i < NN) ? g_degcnt[i] : 0;
    int inc = c;
    #pragma unroll
    for (int d = 1; d < 32; d <<= 1) {
        int t = __shfl_up_sync(0xffffffffu, inc, d);
        if (lane >= d) inc += t;
    }
    if (lane == 31) winc[wid] = inc;
    __syncthreads();
    if (wid == 0) {
        int v = winc[lane];
        int vi = v;
        #pragma unroll
        for (int d = 1; d < 32; d <<= 1) {
            int t = __shfl_up_sync(0xffffffffu, vi, d);
            if (lane >= d) vi += t;
        }
        woff[lane] = vi - v;
    }
    __syncthreads();
    if (i < NN) {
        int run = sexcl[blockIdx.x] + woff[wid] + (inc - c);
        g_rowptr[i] = run;
        g_fill[i]   = run;
        g_invdeg[i] = 1.0f / (float)(c + 1);
    }
    if (blockIdx.x == 0 && tid == 0) g_rowptr[NN] = stotal;
}

// CSR fill, 2 edges/thread
__global__ void k_fill(const int* __restrict__ ei) {
    int t = blockIdx.x * blockDim.x + threadIdx.x;
    int e = t * 2;
    #pragma unroll
    for (int k = 0; k < 2; k++) {
        int ee = e + k;
        if (ee < EE) {
            int r = ei[ee];
            int c = ei[EE + ee];
            if ((unsigned)r < NN && (unsigned)c < NN) {
                int p = atomicAdd(&g_fill[r], 1);
                if ((unsigned)p < EE) g_col[p] = c;
            }
        }
    }
}

// ---------------------------------------------------------------------------
// Fused dropout-multiply + fp16 convert + GEMM:  z = (x*dm) @ W1
__global__ __launch_bounds__(256) void k_gemm_fused(const float* __restrict__ x,
                                                    const float* __restrict__ dm) {
    __shared__ __align__(16) __half As[64][KC + 8];
    __shared__ __align__(16) __half Bs[KC][HH + 8];
    int tid = threadIdx.x;
    int warp = tid >> 5, lane = tid & 31;
    int wm = warp >> 2;
    int wn = warp & 3;
    int m0 = blockIdx.x * 64;

    wmma::fragment<wmma::accumulator, 16, 16, 16, float> c[2][4];
    #pragma unroll
    for (int i = 0; i < 2; i++)
        #pragma unroll
        for (int j = 0; j < 4; j++) wmma::fill_fragment(c[i][j], 0.f);

    for (int kk = 0; kk < HH; kk += KC) {
        #pragma unroll
        for (int i = 0; i < 2; i++) {
            int idx = tid + i * 256;
            int row = idx >> 3;
            int c4  = (idx & 7) * 4;
            int grow = m0 + row;
            __half2 h0, h1;
            if (grow < NN) {
                float4 xv = *(const float4*)(x  + (size_t)grow * HH + kk + c4);
                float4 dv = *(const float4*)(dm + (size_t)grow * HH + kk + c4);
                h0 = __floats2half2_rn(xv.x*dv.x, xv.y*dv.y);
                h1 = __floats2half2_rn(xv.z*dv.z, xv.w*dv.w);
            } else {
                h0 = __floats2half2_rn(0.f, 0.f);
                h1 = h0;
            }
            *(__half2*)&As[row][c4]     = h0;
            *(__half2*)&As[row][c4 + 2] = h1;
        }
        #pragma unroll
        for (int i = 0; i < 4; i++) {
            int idx = tid + i * 256;
            int row = idx >> 5;
            int c8  = (idx & 31) * 8;
            *(uint4*)&Bs[row][c8] = *(const uint4*)(g_w1h + (size_t)(kk + row) * HH + c8);
        }
        __syncthreads();
        #pragma unroll
        for (int ks = 0; ks < KC; ks += 16) {
            wmma::fragment<wmma::matrix_a, 16, 16, 16, __half, wmma::row_major> a[2];
            #pragma unroll
            for (int i = 0; i < 2; i++)
                wmma::load_matrix_sync(a[i], &As[wm*32 + 16*i][ks], KC + 8);
            #pragma unroll
            for (int j = 0; j < 4; j++) {
                wmma::fragment<wmma::matrix_b, 16, 16, 16, __half, wmma::row_major> b;
                wmma::load_matrix_sync(b, &Bs[ks][wn*64 + 16*j], HH + 8);
                wmma::mma_sync(c[0][j], a[0], b, c[0][j]);
                wmma::mma_sync(c[1][j], a[1], b, c[1][j]);
            }
        }
        __syncthreads();
    }

    float* stg = (float*)Bs + warp * 320;
    #pragma unroll
    for (int i = 0; i < 2; i++)
        #pragma unroll
        for (int j = 0; j < 4; j++) {
            wmma::store_matrix_sync(stg, c[i][j], 20, wmma::mem_row_major);
            __syncwarp();
            if (lane < 16) {
                const float* sr = stg + lane * 20;
                __half2 hh[8];
                #pragma unroll
                for (int p = 0; p < 8; p++)
                    hh[p] = __floats2half2_rn(sr[2*p], sr[2*p+1]);
                int gr = m0 + wm*32 + i*16 + lane;
                __half* dst = g_z + (size_t)gr * HH + wn*64 + j*16;
                ((uint4*)dst)[0] = ((uint4*)hh)[0];
                ((uint4*)dst)[1] = ((uint4*)hh)[1];
            }
            __syncwarp();
        }
}

// ---------------------------------------------------------------------------
// half2 accumulate helpers
__device__ __forceinline__ void hacc4(__half2 a[4], uint4 raw) {
    __half2* h = (__half2*)&raw;
    a[0] = __hadd2(a[0], h[0]);
    a[1] = __hadd2(a[1], h[1]);
    a[2] = __hadd2(a[2], h[2]);
    a[3] = __hadd2(a[3], h[3]);
}
__device__ __forceinline__ void hfma4(__half2 a[4], uint4 raw, __half2 m) {
    __half2* h = (__half2*)&raw;
    a[0] = __hfma2(h[0], m, a[0]);
    a[1] = __hfma2(h[1], m, a[1]);
    a[2] = __hfma2(h[2], m, a[2]);
    a[3] = __hfma2(h[3], m, a[3]);
}
// scale (fp32) + evict-first store of 4 half2
__device__ __forceinline__ void store_h2x4_cs(__half* base, int lane, const __half2 a[4], float inv) {
    __half2 h[4];
    #pragma unroll
    for (int p = 0; p < 4; p++) {
        float2 f = __half22float2(a[p]);
        h[p] = __floats2half2_rn(f.x * inv, f.y * inv);
    }
    __stcs((uint4*)base + lane, *(uint4*)h);
}

// Fused first propagation step for all 4 views; HFMA2 (masks are exactly 0/1).
__global__ __launch_bounds__(256) void k_step1() {
    int gw = (blockIdx.x * blockDim.x + threadIdx.x) >> 5;
    int lane = threadIdx.x & 31;
    if (gw >= NN) return;
    int r = gw;

    uint4 sz = ((const uint4*)(g_z + (size_t)r * HH))[lane];
    __half2* szh = (__half2*)&sz;

    uint2 mr = g_mask4h[r];
    const __half* mrh = (const __half*)&mr;

    __half2 a[VV][4];
    #pragma unroll
    for (int v = 0; v < VV; v++) {
        __half2 mh = __half2half2(mrh[v]);
        #pragma unroll
        for (int k = 0; k < 4; k++) a[v][k] = __hmul2(szh[k], mh);
    }

    int jb = g_rowptr[r], je = g_rowptr[r + 1];
    int j = jb;
    for (; j + 1 < je; j += 2) {
        int c0 = g_col[j], c1 = g_col[j + 1];
        uint4 z0 = ((const uint4*)(g_z + (size_t)c0 * HH))[lane];
        uint4 z1 = ((const uint4*)(g_z + (size_t)c1 * HH))[lane];
        uint2 m0 = g_mask4h[c0];
        uint2 m1 = g_mask4h[c1];
        const __half* m0h = (const __half*)&m0;
        const __half* m1h = (const __half*)&m1;
        #pragma unroll
        for (int v = 0; v < VV; v++) {
            hfma4(a[v], z0, __half2half2(m0h[v]));
            hfma4(a[v], z1, __half2half2(m1h[v]));
        }
    }
    if (j < je) {
        int c = g_col[j];
        uint4 z0 = ((const uint4*)(g_z + (size_t)c * HH))[lane];
        uint2 m0 = g_mask4h[c];
        const __half* m0h = (const __half*)&m0;
        #pragma unroll
        for (int v = 0; v < VV; v++)
            hfma4(a[v], z0, __half2half2(m0h[v]));
    }
    float inv = g_invdeg[r];
    #pragma unroll
    for (int v = 0; v < VV; v++)
        store_h2x4_cs(g_pairs[v >> 1] + (size_t)r * PH + (v & 1) * HH, lane, a[v], inv);
}

// one propagation step for one view-pair; HADD2 accumulation.
__global__ __launch_bounds__(256) void k_spmm2(int pair, int dir) {
    const __half* in = dir ? g_ptmp[pair] : g_pairs[pair];
    __half* out      = dir ? g_pairs[pair] : g_ptmp[pair];

    int gw = (blockIdx.x * blockDim.x + threadIdx.x) >> 5;
    int lane = threadIdx.x & 31;
    if (gw >= NN) return;
    int r = gw;

    const uint4* sp = (const uint4*)(in + (size_t)r * PH);
    uint4 s0 = sp[lane], s1 = sp[lane + 32];
    __half2 a0[4], a1[4];
    *(uint4*)a0 = s0;
    *(uint4*)a1 = s1;

    int jb = g_rowptr[r], je = g_rowptr[r + 1];
    int j = jb;
    for (; j + 1 < je; j += 2) {
        int c0 = g_col[j], c1 = g_col[j + 1];
        const uint4* p0 = (const uint4*)(in + (size_t)c0 * PH);
        const uint4* p1 = (const uint4*)(in + (size_t)c1 * PH);
        uint4 r00 = p0[lane], r01 = p0[lane + 32];
        uint4 r10 = p1[lane], r11 = p1[lane + 32];
        hacc4(a0, r00); hacc4(a1, r01);
        hacc4(a0, r10); hacc4(a1, r11);
    }
    if (j < je) {
        int c = g_col[j];
        const uint4* p = (const uint4*)(in + (size_t)c * PH);
        uint4 u0 = p[lane], u1 = p[lane + 32];
        hacc4(a0, u0);
        hacc4(a1, u1);
    }
    float inv = g_invdeg[r];
    __half* orow = out + (size_t)r * PH;
    store_h2x4_cs(orow,      lane, a0, inv);
    store_h2x4_cs(orow + HH, lane, a1, inv);
}

// ---------------------------------------------------------------------------
// pooled[v][b][f] += relu(state[r][v][f] + b1[f]) for batch[r]==b
__global__ __launch_bounds__(256) void k_pool(const int* __restrict__ batch,
                                              const float* __restrict__ b1, int v0) {
    int v  = v0 + blockIdx.y;
    int f  = threadIdx.x;
    int r0 = blockIdx.x * 64;
    const __half* in = g_pairs[v >> 1] + (size_t)(v & 1) * HH;
    float bias = b1[f];
    float acc = 0.f;
    int curb = -1;
    int rend = r0 + 64; if (rend > NN) rend = NN;
    for (int r = r0; r < rend; r++) {
        int b = batch[r];
        if ((unsigned)b >= BB) continue;
        if (b != curb) {
            if (curb >= 0) atomicAdd(&g_pool[(curb + v * BB) * HH + f], acc);
            acc = 0.f; curb = b;
        }
        float val = __half2float(in[(size_t)r * PH + f]) + bias;
        acc += fmaxf(val, 0.f);
    }
    if (curb >= 0) atomicAdd(&g_pool[(curb + v * BB) * HH + f], acc);
}

__global__ __launch_bounds__(256) void k_head(const float* __restrict__ W2,
                                              const float* __restrict__ b2,
                                              const float* __restrict__ Wc,
                                              const float* __restrict__ bcv,
                                              float* __restrict__ out) {
    __shared__ float sp[HH];
    __shared__ float sy[HH];
    __shared__ float slog[CC];
    int vb = blockIdx.x;
    int v = vb >> 7, b = vb & 127;
    int tid = threadIdx.x;

    float cnt = (float)g_counts[b];
    if (cnt < 1.f) cnt = 1.f;
    sp[tid] = g_pool[(v * BB + b) * HH + tid] / cnt;
    __syncthreads();

    float acc = b2[tid];
    #pragma unroll 8
    for (int h = 0; h < HH; h++) acc += sp[h] * W2[h * HH + tid];
    sy[tid] = acc;
    __syncthreads();

    if (tid < CC) {
        float l = bcv[tid];
        #pragma unroll 8
        for (int h = 0; h < HH; h++) l += sy[h] * Wc[h * CC + tid];
        slog[tid] = l;
    }
    __syncthreads();

    if (tid == 0) {
        float mx = -1e30f;
        #pragma unroll
        for (int c = 0; c < CC; c++) mx = fmaxf(mx, slog[c]);
        float s = 0.f, e[CC];
        #pragma unroll
        for (int c = 0; c < CC; c++) { e[c] = expf(slog[c] - mx); s += e[c]; }
        float invs = 1.f / s;
        #pragma unroll
        for (int c = 0; c < CC; c++) g_probs[(v * BB + b) * CC + c] = e[c] * invs;
        if (v == 0) {
            #pragma unroll
            for (int c = 0; c < CC; c++) out[b * CC + c] = slog[c];
        }
    }
}

__global__ void k_loss(float* __restrict__ out, int out_size) {
    __shared__ float sc[BB], se[BB];
    int b = threadIdx.x;
    float mp[CC];
    #pragma unroll
    for (int c = 0; c < CC; c++) {
        float s = 0.f;
        #pragma unroll
        for (int v = 0; v < VV; v++) s += g_probs[(v * BB + b) * CC + c];
        mp[c] = s * (1.0f / VV);
    }
    float cons = 0.f;
    #pragma unroll
    for (int v = 0; v < VV; v++)
        #pragma unroll
        for (int c = 0; c < CC; c++) {
            float d = g_probs[(v * BB + b) * CC + c] - mp[c];
            cons += d * d;
        }
    float ent = 0.f;
    #pragma unroll
    for (int c = 0; c < CC; c++) ent -= mp[c] * logf(mp[c] + 1e-8f);
    sc[b] = cons; se[b] = ent;
    __syncthreads();
    for (int s = 64; s > 0; s >>= 1) {
        if (b < s) { sc[b] += sc[b + s]; se[b] += se[b + s]; }
        __syncthreads();
    }
    if (b == 0)
        out[out_size - 1] = 1.0f * (sc[0] / (float)(VV * BB)) + se[0] / (float)BB;
}

// ---------------------------------------------------------------------------
extern "C" void kernel_launch(void* const* d_in, const int* in_sizes, int n_in,
                              void* d_out, int out_size) {
    const float* x     = (const float*)d_in[0];
    const int*   ei    = (const int*)d_in[1];
    const int*   batch = (const int*)d_in[2];
    const float* dm    = (const float*)d_in[3];
    const float* masks = (const float*)d_in[4];
    const float* W1    = (const float*)d_in[5];
    const float* b1    = (const float*)d_in[6];
    const float* W2    = (const float*)d_in[7];
    const float* b2    = (const float*)d_in[8];
    const float* Wc    = (const float*)d_in[9];
    const float* bcv   = (const float*)d_in[10];
    float* out = (float*)d_out;

    // fork/join streams & events (host objects only; graph-capture-legal).
    cudaStream_t s2;
    cudaStreamCreate(&s2);
    cudaEvent_t eFork, eJoin, eP0, eP01;
    cudaEventCreateWithFlags(&eFork, cudaEventDisableTiming);
    cudaEventCreateWithFlags(&eJoin, cudaEventDisableTiming);
    cudaEventCreateWithFlags(&eP0,   cudaEventDisableTiming);
    cudaEventCreateWithFlags(&eP01,  cudaEventDisableTiming);

    // fork immediately: side stream does pool-zero + W1 convert + GEMM,
    // main stream does the CSR chain. The arms are fully independent.
    cudaEventRecord(eFork, 0);
    cudaStreamWaitEvent(s2, eFork, 0);

    k_zero_aux<<<(VV*BB*HH + 255) / 256, 256, 0, s2>>>(W1);
    k_gemm_fused<<<NPAD / 64, 256, 0, s2>>>(x, dm);
    cudaEventRecord(eJoin, s2);

    k_zero_main<<<(NN + 255) / 256, 256>>>();
    k_hist<<<(EE/2 + 255) / 256, 256>>>(ei, batch, masks);
    k_scan_a<<<SCB, 1024>>>();
    k_scan_c<<<SCB, 1024>>>();
    k_fill<<<(EE/2 + 255) / 256, 256>>>(ei);

    cudaStreamWaitEvent(0, eJoin, 0);                 // join before step1

    int wgrid = (NN * 32 + 255) / 256;
    dim3 pgrid((NN + 63) / 64, 2);                    // 2 views per pool launch

    k_step1<<<wgrid, 256>>>();
    k_spmm2<<<wgrid, 256>>>(0, 0);   // pair0 step2
    k_spmm2<<<wgrid, 256>>>(0, 1);   // pair0 step3

    // fork: pool views {0,1} on side stream while pair1 propagates
    cudaEventRecord(eP0, 0);
    cudaStreamWaitEvent(s2, eP0, 0);
    k_pool<<<pgrid, 256, 0, s2>>>(batch, b1, 0);
    cudaEventRecord(eP01, s2);

    k_spmm2<<<wgrid, 256>>>(1, 0);   // pair1 step2
    k_spmm2<<<wgrid, 256>>>(1, 1);   // pair1 step3
    k_pool<<<pgrid, 256>>>(batch, b1, 2);   // views {2,3}

    cudaStreamWaitEvent(0, eP01, 0);                  // join pool01 before head

    k_head<<<VV * BB, 256>>>(W2, b2, Wc, bcv, out);
    k_loss<<<1, BB>>>(out, out_size);
}

// round 15
// speedup vs baseline: 1.1189x; 1.0105x over previous
#include <cuda_runtime.h>
#include <cuda_fp16.h>
#include <mma.h>
using namespace nvcuda;

#define NN 50000
#define NPAD 50048            // 782 * 64, pad for wmma tiles
#define EE 800000
#define HH 256
#define BB 128
#define VV 4
#define CC 10
#define PH 512                // pair row width: 2 views * 256 feats
#define KC 32                 // gemm k-chunk
#define SCB 49                // scan blocks: 49*1024 >= NN

// ---- scratch (device globals; no allocation allowed) ----
__device__ int    g_degcnt[NN];
__device__ int    g_rowptr[NN+1];
__device__ int    g_fill[NN];
__device__ float  g_invdeg[NN];
__device__ int    g_col[EE];
__device__ int    g_counts[BB];
__device__ int    g_part[SCB];              // scan partials (raw block sums)
__device__ uint2  g_mask4h[NN];             // node masks as 4 x half (exactly 0/1)
__device__ __half g_w1h[HH*HH];             // W1 fp16
__device__ __half g_z[NPAD*HH];             // (x*dropout) @ W1, fp16
__device__ __half g_pairs[2][(size_t)NN*PH]; // view pairs {0,1},{2,3}
__device__ __half g_ptmp[2][(size_t)NN*PH];  // ping-pong per pair
__device__ float  g_pool[VV*BB*HH];
__device__ float  g_probs[VV*BB*CC];

// ---------------------------------------------------------------------------
// main-stream zero: only what the CSR chain needs
__global__ void k_zero_main() {
    int i = blockIdx.x * blockDim.x + threadIdx.x;
    if (i < NN) g_degcnt[i] = 0;
    if (i < BB) g_counts[i] = 0;
}

// side-stream aux: pool zero + W1 convert + batch counts + mask transpose.
// None of these feed the CSR chain; they only gate step1/head (after join).
__global__ void k_zero_aux(const float* __restrict__ W1,
                           const int* __restrict__ batch,
                           const float* __restrict__ masks) {
    int i = blockIdx.x * blockDim.x + threadIdx.x;
    if (i < VV*BB*HH) g_pool[i] = 0.f;
    if (i < HH*HH/4) {
        float4 w = *(const float4*)(W1 + i * 4);
        __half2 h[2];
        h[0] = __floats2half2_rn(w.x, w.y);
        h[1] = __floats2half2_rn(w.z, w.w);
        *(uint2*)(g_w1h + i * 4) = *(uint2*)h;
    }
    if (i < NN) {
        int b = batch[i];
        if ((unsigned)b < BB) atomicAdd(&g_counts[b], 1);
        __half2 p01 = __floats2half2_rn(masks[i],        masks[NN + i]);
        __half2 p23 = __floats2half2_rn(masks[2*NN + i], masks[3*NN + i]);
        uint2 u;
        *(__half2*)&u.x = p01;
        *(__half2*)&u.y = p23;
        g_mask4h[i] = u;
    }
}

// edge-row histogram only, 1 edge/thread (max threads for atomic latency hiding)
__global__ void k_hist(const int* __restrict__ ei) {
    int e = blockIdx.x * blockDim.x + threadIdx.x;
    if (e < EE) {
        int r = ei[e];
        if ((unsigned)r < NN) atomicAdd(&g_degcnt[r], 1);
    }
}

// ---- 2-phase grid-wide exclusive scan of g_degcnt -------------------------
// phase a: per-block sums
__global__ __launch_bounds__(1024) void k_scan_a() {
    __shared__ int wsum[32];
    int i = blockIdx.x * 1024 + threadIdx.x;
    int lane = threadIdx.x & 31, wid = threadIdx.x >> 5;
    int c = (i < NN) ? g_degcnt[i] : 0;
    int s = c;
    #pragma unroll
    for (int d = 16; d > 0; d >>= 1) s += __shfl_down_sync(0xffffffffu, s, d);
    if (lane == 0) wsum[wid] = s;
    __syncthreads();
    if (wid == 0) {
        int t = wsum[lane];
        #pragma unroll
        for (int d = 16; d > 0; d >>= 1) t += __shfl_down_sync(0xffffffffu, t, d);
        if (lane == 0) g_part[blockIdx.x] = t;
    }
}

// phase c: each block redundantly scans the 49 partials (threads 0-63), then
// block-exclusive scan + offset -> rowptr/fill/invdeg.
__global__ __launch_bounds__(1024) void k_scan_c() {
    __shared__ int winc[32];
    __shared__ int woff[32];
    __shared__ int sexcl[64];
    __shared__ int stotal;
    int tid = threadIdx.x;
    int lane = tid & 31, wid = tid >> 5;

    // -- partial scan (threads 0..63, two warps) --
    if (tid < 64) {
        int v = (tid < SCB) ? g_part[tid] : 0;
        int inc = v;
        #pragma unroll
        for (int d = 1; d < 32; d <<= 1) {
            int t = __shfl_up_sync(0xffffffffu, inc, d);
            if (lane >= d) inc += t;
        }
        if (lane == 31) winc[wid] = inc;
    }
    __syncthreads();
    if (tid < 64) {
        int v = (tid < SCB) ? g_part[tid] : 0;
        int inc = v;
        #pragma unroll
        for (int d = 1; d < 32; d <<= 1) {
            int t = __shfl_up_sync(0xffffffffu, inc, d);
            if (lane >= d) inc += t;
        }
        int off = (wid == 1) ? winc[0] : 0;
        sexcl[tid] = off + inc - v;
        if (tid == 63) stotal = winc[0] + winc[1];
    }
    __syncthreads();

    // -- per-element scan --
    int i = blockIdx.x * 1024 + tid;
    int c = (i < NN) ? g_degcnt[i] : 0;
    int inc = c;
    #pragma unroll
    for (int d = 1; d < 32; d <<= 1) {
        int t = __shfl_up_sync(0xffffffffu, inc, d);
        if (lane >= d) inc += t;
    }
    if (lane == 31) winc[wid] = inc;
    __syncthreads();
    if (wid == 0) {
        int v = winc[lane];
        int vi = v;
        #pragma unroll
        for (int d = 1; d < 32; d <<= 1) {
            int t = __shfl_up_sync(0xffffffffu, vi, d);
            if (lane >= d) vi += t;
        }
        woff[lane] = vi - v;
    }
    __syncthreads();
    if (i < NN) {
        int run = sexcl[blockIdx.x] + woff[wid] + (inc - c);
        g_rowptr[i] = run;
        g_fill[i]   = run;
        g_invdeg[i] = 1.0f / (float)(c + 1);
    }
    if (blockIdx.x == 0 && tid == 0) g_rowptr[NN] = stotal;
}

// CSR fill, 1 edge/thread
__global__ void k_fill(const int* __restrict__ ei) {
    int e = blockIdx.x * blockDim.x + threadIdx.x;
    if (e < EE) {
        int r = ei[e];
        int c = ei[EE + e];
        if ((unsigned)r < NN && (unsigned)c < NN) {
            int p = atomicAdd(&g_fill[r], 1);
            if ((unsigned)p < EE) g_col[p] = c;
        }
    }
}

// ---------------------------------------------------------------------------
// Fused dropout-multiply + fp16 convert + GEMM:  z = (x*dm) @ W1
__global__ __launch_bounds__(256) void k_gemm_fused(const float* __restrict__ x,
                                                    const float* __restrict__ dm) {
    __shared__ __align__(16) __half As[64][KC + 8];
    __shared__ __align__(16) __half Bs[KC][HH + 8];
    int tid = threadIdx.x;
    int warp = tid >> 5, lane = tid & 31;
    int wm = warp >> 2;
    int wn = warp & 3;
    int m0 = blockIdx.x * 64;

    wmma::fragment<wmma::accumulator, 16, 16, 16, float> c[2][4];
    #pragma unroll
    for (int i = 0; i < 2; i++)
        #pragma unroll
        for (int j = 0; j < 4; j++) wmma::fill_fragment(c[i][j], 0.f);

    for (int kk = 0; kk < HH; kk += KC) {
        #pragma unroll
        for (int i = 0; i < 2; i++) {
            int idx = tid + i * 256;
            int row = idx >> 3;
            int c4  = (idx & 7) * 4;
            int grow = m0 + row;
            __half2 h0, h1;
            if (grow < NN) {
                float4 xv = *(const float4*)(x  + (size_t)grow * HH + kk + c4);
                float4 dv = *(const float4*)(dm + (size_t)grow * HH + kk + c4);
                h0 = __floats2half2_rn(xv.x*dv.x, xv.y*dv.y);
                h1 = __floats2half2_rn(xv.z*dv.z, xv.w*dv.w);
            } else {
                h0 = __floats2half2_rn(0.f, 0.f);
                h1 = h0;
            }
            *(__half2*)&As[row][c4]     = h0;
            *(__half2*)&As[row][c4 + 2] = h1;
        }
        #pragma unroll
        for (int i = 0; i < 4; i++) {
            int idx = tid + i * 256;
            int row = idx >> 5;
            int c8  = (idx & 31) * 8;
            *(uint4*)&Bs[row][c8] = *(const uint4*)(g_w1h + (size_t)(kk + row) * HH + c8);
        }
        __syncthreads();
        #pragma unroll
        for (int ks = 0; ks < KC; ks += 16) {
            wmma::fragment<wmma::matrix_a, 16, 16, 16, __half, wmma::row_major> a[2];
            #pragma unroll
            for (int i = 0; i < 2; i++)
                wmma::load_matrix_sync(a[i], &As[wm*32 + 16*i][ks], KC + 8);
            #pragma unroll
            for (int j = 0; j < 4; j++) {
                wmma::fragment<wmma::matrix_b, 16, 16, 16, __half, wmma::row_major> b;
                wmma::load_matrix_sync(b, &Bs[ks][wn*64 + 16*j], HH + 8);
                wmma::mma_sync(c[0][j], a[0], b, c[0][j]);
                wmma::mma_sync(c[1][j], a[1], b, c[1][j]);
            }
        }
        __syncthreads();
    }

    float* stg = (float*)Bs + warp * 320;
    #pragma unroll
    for (int i = 0; i < 2; i++)
        #pragma unroll
        for (int j = 0; j < 4; j++) {
            wmma::store_matrix_sync(stg, c[i][j], 20, wmma::mem_row_major);
            __syncwarp();
            if (lane < 16) {
                const float* sr = stg + lane * 20;
                __half2 hh[8];
                #pragma unroll
                for (int p = 0; p < 8; p++)
                    hh[p] = __floats2half2_rn(sr[2*p], sr[2*p+1]);
                int gr = m0 + wm*32 + i*16 + lane;
                __half* dst = g_z + (size_t)gr * HH + wn*64 + j*16;
                ((uint4*)dst)[0] = ((uint4*)hh)[0];
                ((uint4*)dst)[1] = ((uint4*)hh)[1];
            }
            __syncwarp();
        }
}

// ---------------------------------------------------------------------------
// half2 accumulate helpers
__device__ __forceinline__ void hacc4(__half2 a[4], uint4 raw) {
    __half2* h = (__half2*)&raw;
    a[0] = __hadd2(a[0], h[0]);
    a[1] = __hadd2(a[1], h[1]);
    a[2] = __hadd2(a[2], h[2]);
    a[3] = __hadd2(a[3], h[3]);
}
__device__ __forceinline__ void hfma4(__half2 a[4], uint4 raw, __half2 m) {
    __half2* h = (__half2*)&raw;
    a[0] = __hfma2(h[0], m, a[0]);
    a[1] = __hfma2(h[1], m, a[1]);
    a[2] = __hfma2(h[2], m, a[2]);
    a[3] = __hfma2(h[3], m, a[3]);
}
// scale (fp32) + evict-first store of 4 half2
__device__ __forceinline__ void store_h2x4_cs(__half* base, int lane, const __half2 a[4], float inv) {
    __half2 h[4];
    #pragma unroll
    for (int p = 0; p < 4; p++) {
        float2 f = __half22float2(a[p]);
        h[p] = __floats2half2_rn(f.x * inv, f.y * inv);
    }
    __stcs((uint4*)base + lane, *(uint4*)h);
}

// Fused first propagation step for all 4 views; HFMA2 (masks are exactly 0/1).
__global__ __launch_bounds__(256) void k_step1() {
    int gw = (blockIdx.x * blockDim.x + threadIdx.x) >> 5;
    int lane = threadIdx.x & 31;
    if (gw >= NN) return;
    int r = gw;

    uint4 sz = ((const uint4*)(g_z + (size_t)r * HH))[lane];
    __half2* szh = (__half2*)&sz;

    uint2 mr = g_mask4h[r];
    const __half* mrh = (const __half*)&mr;

    __half2 a[VV][4];
    #pragma unroll
    for (int v = 0; v < VV; v++) {
        __half2 mh = __half2half2(mrh[v]);
        #pragma unroll
        for (int k = 0; k < 4; k++) a[v][k] = __hmul2(szh[k], mh);
    }

    int jb = g_rowptr[r], je = g_rowptr[r + 1];
    int j = jb;
    for (; j + 1 < je; j += 2) {
        int c0 = g_col[j], c1 = g_col[j + 1];
        uint4 z0 = ((const uint4*)(g_z + (size_t)c0 * HH))[lane];
        uint4 z1 = ((const uint4*)(g_z + (size_t)c1 * HH))[lane];
        uint2 m0 = g_mask4h[c0];
        uint2 m1 = g_mask4h[c1];
        const __half* m0h = (const __half*)&m0;
        const __half* m1h = (const __half*)&m1;
        #pragma unroll
        for (int v = 0; v < VV; v++) {
            hfma4(a[v], z0, __half2half2(m0h[v]));
            hfma4(a[v], z1, __half2half2(m1h[v]));
        }
    }
    if (j < je) {
        int c = g_col[j];
        uint4 z0 = ((const uint4*)(g_z + (size_t)c * HH))[lane];
        uint2 m0 = g_mask4h[c];
        const __half* m0h = (const __half*)&m0;
        #pragma unroll
        for (int v = 0; v < VV; v++)
            hfma4(a[v], z0, __half2half2(m0h[v]));
    }
    float inv = g_invdeg[r];
    #pragma unroll
    for (int v = 0; v < VV; v++)
        store_h2x4_cs(g_pairs[v >> 1] + (size_t)r * PH + (v & 1) * HH, lane, a[v], inv);
}

// one propagation step for one view-pair; HADD2 accumulation.
__global__ __launch_bounds__(256) void k_spmm2(int pair, int dir) {
    const __half* in = dir ? g_ptmp[pair] : g_pairs[pair];
    __half* out      = dir ? g_pairs[pair] : g_ptmp[pair];

    int gw = (blockIdx.x * blockDim.x + threadIdx.x) >> 5;
    int lane = threadIdx.x & 31;
    if (gw >= NN) return;
    int r = gw;

    const uint4* sp = (const uint4*)(in + (size_t)r * PH);
    uint4 s0 = sp[lane], s1 = sp[lane + 32];
    __half2 a0[4], a1[4];
    *(uint4*)a0 = s0;
    *(uint4*)a1 = s1;

    int jb = g_rowptr[r], je = g_rowptr[r + 1];
    int j = jb;
    for (; j + 1 < je; j += 2) {
        int c0 = g_col[j], c1 = g_col[j + 1];
        const uint4* p0 = (const uint4*)(in + (size_t)c0 * PH);
        const uint4* p1 = (const uint4*)(in + (size_t)c1 * PH);
        uint4 r00 = p0[lane], r01 = p0[lane + 32];
        uint4 r10 = p1[lane], r11 = p1[lane + 32];
        hacc4(a0, r00); hacc4(a1, r01);
        hacc4(a0, r10); hacc4(a1, r11);
    }
    if (j < je) {
        int c = g_col[j];
        const uint4* p = (const uint4*)(in + (size_t)c * PH);
        uint4 u0 = p[lane], u1 = p[lane + 32];
        hacc4(a0, u0);
        hacc4(a1, u1);
    }
    float inv = g_invdeg[r];
    __half* orow = out + (size_t)r * PH;
    store_h2x4_cs(orow,      lane, a0, inv);
    store_h2x4_cs(orow + HH, lane, a1, inv);
}

// ---------------------------------------------------------------------------
// pooled[v][b][f] += relu(state[r][v][f] + b1[f]) for batch[r]==b
__global__ __launch_bounds__(256) void k_pool(const int* __restrict__ batch,
                                              const float* __restrict__ b1, int v0) {
    int v  = v0 + blockIdx.y;
    int f  = threadIdx.x;
    int r0 = blockIdx.x * 64;
    const __half* in = g_pairs[v >> 1] + (size_t)(v & 1) * HH;
    float bias = b1[f];
    float acc = 0.f;
    int curb = -1;
    int rend = r0 + 64; if (rend > NN) rend = NN;
    for (int r = r0; r < rend; r++) {
        int b = batch[r];
        if ((unsigned)b >= BB) continue;
        if (b != curb) {
            if (curb >= 0) atomicAdd(&g_pool[(curb + v * BB) * HH + f], acc);
            acc = 0.f; curb = b;
        }
        float val = __half2float(in[(size_t)r * PH + f]) + bias;
        acc += fmaxf(val, 0.f);
    }
    if (curb >= 0) atomicAdd(&g_pool[(curb + v * BB) * HH + f], acc);
}

__global__ __launch_bounds__(256) void k_head(const float* __restrict__ W2,
                                              const float* __restrict__ b2,
                                              const float* __restrict__ Wc,
                                              const float* __restrict__ bcv,
                                              float* __restrict__ out) {
    __shared__ float sp[HH];
    __shared__ float sy[HH];
    __shared__ float slog[CC];
    int vb = blockIdx.x;
    int v = vb >> 7, b = vb & 127;
    int tid = threadIdx.x;

    float cnt = (float)g_counts[b];
    if (cnt < 1.f) cnt = 1.f;
    sp[tid] = g_pool[(v * BB + b) * HH + tid] / cnt;
    __syncthreads();

    float acc = b2[tid];
    #pragma unroll 8
    for (int h = 0; h < HH; h++) acc += sp[h] * W2[h * HH + tid];
    sy[tid] = acc;
    __syncthreads();

    if (tid < CC) {
        float l = bcv[tid];
        #pragma unroll 8
        for (int h = 0; h < HH; h++) l += sy[h] * Wc[h * CC + tid];
        slog[tid] = l;
    }
    __syncthreads();

    if (tid == 0) {
        float mx = -1e30f;
        #pragma unroll
        for (int c = 0; c < CC; c++) mx = fmaxf(mx, slog[c]);
        float s = 0.f, e[CC];
        #pragma unroll
        for (int c = 0; c < CC; c++) { e[c] = expf(slog[c] - mx); s += e[c]; }
        float invs = 1.f / s;
        #pragma unroll
        for (int c = 0; c < CC; c++) g_probs[(v * BB + b) * CC + c] = e[c] * invs;
        if (v == 0) {
            #pragma unroll
            for (int c = 0; c < CC; c++) out[b * CC + c] = slog[c];
        }
    }
}

__global__ void k_loss(float* __restrict__ out, int out_size) {
    __shared__ float sc[BB], se[BB];
    int b = threadIdx.x;
    float mp[CC];
    #pragma unroll
    for (int c = 0; c < CC; c++) {
        float s = 0.f;
        #pragma unroll
        for (int v = 0; v < VV; v++) s += g_probs[(v * BB + b) * CC + c];
        mp[c] = s * (1.0f / VV);
    }
    float cons = 0.f;
    #pragma unroll
    for (int v = 0; v < VV; v++)
        #pragma unroll
        for (int c = 0; c < CC; c++) {
            float d = g_probs[(v * BB + b) * CC + c] - mp[c];
            cons += d * d;
        }
    float ent = 0.f;
    #pragma unroll
    for (int c = 0; c < CC; c++) ent -= mp[c] * logf(mp[c] + 1e-8f);
    sc[b] = cons; se[b] = ent;
    __syncthreads();
    for (int s = 64; s > 0; s >>= 1) {
        if (b < s) { sc[b] += sc[b + s]; se[b] += se[b + s]; }
        __syncthreads();
    }
    if (b == 0)
        out[out_size - 1] = 1.0f * (sc[0] / (float)(VV * BB)) + se[0] / (float)BB;
}

// ---------------------------------------------------------------------------
extern "C" void kernel_launch(void* const* d_in, const int* in_sizes, int n_in,
                              void* d_out, int out_size) {
    const float* x     = (const float*)d_in[0];
    const int*   ei    = (const int*)d_in[1];
    const int*   batch = (const int*)d_in[2];
    const float* dm    = (const float*)d_in[3];
    const float* masks = (const float*)d_in[4];
    const float* W1    = (const float*)d_in[5];
    const float* b1    = (const float*)d_in[6];
    const float* W2    = (const float*)d_in[7];
    const float* b2    = (const float*)d_in[8];
    const float* Wc    = (const float*)d_in[9];
    const float* bcv   = (const float*)d_in[10];
    float* out = (float*)d_out;

    // fork/join streams & events (host objects only; graph-capture-legal).
    cudaStream_t s2;
    cudaStreamCreate(&s2);
    cudaEvent_t eFork, eJoin, eP0, eP01;
    cudaEventCreateWithFlags(&eFork, cudaEventDisableTiming);
    cudaEventCreateWithFlags(&eJoin, cudaEventDisableTiming);
    cudaEventCreateWithFlags(&eP0,   cudaEventDisableTiming);
    cudaEventCreateWithFlags(&eP01,  cudaEventDisableTiming);

    // k_zero_main must precede k_zero_aux's atomic counts (g_counts zeroing);
    // so: zero_main on main stream first, THEN fork.
    k_zero_main<<<(NN + 255) / 256, 256>>>();
    cudaEventRecord(eFork, 0);
    cudaStreamWaitEvent(s2, eFork, 0);

    // side arm: pool zero + W1 convert + counts + mask transpose, then GEMM
    k_zero_aux<<<(VV*BB*HH + 255) / 256, 256, 0, s2>>>(W1, batch, masks);
    k_gemm_fused<<<NPAD / 64, 256, 0, s2>>>(x, dm);
    cudaEventRecord(eJoin, s2);

    // main arm: CSR chain (1 edge/thread for atomic-latency hiding)
    k_hist<<<(EE + 255) / 256, 256>>>(ei);
    k_scan_a<<<SCB, 1024>>>();
    k_scan_c<<<SCB, 1024>>>();
    k_fill<<<(EE + 255) / 256, 256>>>(ei);

    cudaStreamWaitEvent(0, eJoin, 0);                 // join before step1

    int wgrid = (NN * 32 + 255) / 256;
    dim3 pgrid((NN + 63) / 64, 2);                    // 2 views per pool launch

    k_step1<<<wgrid, 256>>>();
    k_spmm2<<<wgrid, 256>>>(0, 0);   // pair0 step2
    k_spmm2<<<wgrid, 256>>>(0, 1);   // pair0 step3

    // fork: pool views {0,1} on side stream while pair1 propagates
    cudaEventRecord(eP0, 0);
    cudaStreamWaitEvent(s2, eP0, 0);
    k_pool<<<pgrid, 256, 0, s2>>>(batch, b1, 0);
    cudaEventRecord(eP01, s2);

    k_spmm2<<<wgrid, 256>>>(1, 0);   // pair1 step2
    k_spmm2<<<wgrid, 256>>>(1, 1);   // pair1 step3
    k_pool<<<pgrid, 256>>>(batch, b1, 2);   // views {2,3}

    cudaStreamWaitEvent(0, eP01, 0);                  // join pool01 before head

    k_head<<<VV * BB, 256>>>(W2, b2, Wc, bcv, out);
    k_loss<<<1, BB>>>(out, out_size);
}

// round 16
// speedup vs baseline: 1.2735x; 1.1382x over previous
#include <cuda_runtime.h>
#include <cuda_fp16.h>
#include <mma.h>
using namespace nvcuda;

#define NN 50000
#define NPAD 50048            // 782 * 64, pad for wmma tiles
#define EE 800000
#define HH 256
#define BB 128
#define VV 4
#define CC 10
#define PH 512                // pair row width: 2 views * 256 feats
#define KC 32                 // gemm k-chunk
#define SCB 49                // scan blocks: 49*1024 >= NN

// ---- scratch (device globals; no allocation allowed) ----
__device__ int    g_degcnt[NN];
__device__ int    g_rowptr[NN+1];
__device__ int    g_fill[NN];
__device__ float  g_invdeg[NN];
__device__ int    g_col[EE];
__device__ int    g_counts[BB];
__device__ int    g_part[SCB];              // scan partials (raw block sums)
__device__ uint2  g_mask4h[NN];             // node masks as 4 x half (exactly 0/1)
__device__ __half g_w1h[HH*HH];             // W1 fp16
__device__ __half g_z[NPAD*HH];             // (x*dropout) @ W1, fp16
__device__ __half g_pairs[2][(size_t)NN*PH]; // view pairs {0,1},{2,3}
__device__ __half g_ptmp[2][(size_t)NN*PH];  // ping-pong per pair
__device__ float  g_pool[VV*BB*HH];
__device__ float  g_probs[VV*BB*CC];

// ---------------------------------------------------------------------------
// main-stream zero: only what the CSR chain needs
__global__ void k_zero_main() {
    int i = blockIdx.x * blockDim.x + threadIdx.x;
    if (i < NN) g_degcnt[i] = 0;
    if (i < BB) g_counts[i] = 0;
}

// side-stream aux: pool zero + W1 convert + batch counts + mask transpose.
__global__ void k_zero_aux(const float* __restrict__ W1,
                           const int* __restrict__ batch,
                           const float* __restrict__ masks) {
    int i = blockIdx.x * blockDim.x + threadIdx.x;
    if (i < VV*BB*HH) g_pool[i] = 0.f;
    if (i < HH*HH/4) {
        float4 w = *(const float4*)(W1 + i * 4);
        __half2 h[2];
        h[0] = __floats2half2_rn(w.x, w.y);
        h[1] = __floats2half2_rn(w.z, w.w);
        *(uint2*)(g_w1h + i * 4) = *(uint2*)h;
    }
    if (i < NN) {
        int b = batch[i];
        if ((unsigned)b < BB) atomicAdd(&g_counts[b], 1);
        __half2 p01 = __floats2half2_rn(masks[i],        masks[NN + i]);
        __half2 p23 = __floats2half2_rn(masks[2*NN + i], masks[3*NN + i]);
        uint2 u;
        *(__half2*)&u.x = p01;
        *(__half2*)&u.y = p23;
        g_mask4h[i] = u;
    }
}

// edge-row histogram only, 1 edge/thread
__global__ void k_hist(const int* __restrict__ ei) {
    int e = blockIdx.x * blockDim.x + threadIdx.x;
    if (e < EE) {
        int r = ei[e];
        if ((unsigned)r < NN) atomicAdd(&g_degcnt[r], 1);
    }
}

// ---- 2-phase grid-wide exclusive scan of g_degcnt -------------------------
__global__ __launch_bounds__(1024) void k_scan_a() {
    __shared__ int wsum[32];
    int i = blockIdx.x * 1024 + threadIdx.x;
    int lane = threadIdx.x & 31, wid = threadIdx.x >> 5;
    int c = (i < NN) ? g_degcnt[i] : 0;
    int s = c;
    #pragma unroll
    for (int d = 16; d > 0; d >>= 1) s += __shfl_down_sync(0xffffffffu, s, d);
    if (lane == 0) wsum[wid] = s;
    __syncthreads();
    if (wid == 0) {
        int t = wsum[lane];
        #pragma unroll
        for (int d = 16; d > 0; d >>= 1) t += __shfl_down_sync(0xffffffffu, t, d);
        if (lane == 0) g_part[blockIdx.x] = t;
    }
}

__global__ __launch_bounds__(1024) void k_scan_c() {
    __shared__ int winc[32];
    __shared__ int woff[32];
    __shared__ int sexcl[64];
    __shared__ int stotal;
    int tid = threadIdx.x;
    int lane = tid & 31, wid = tid >> 5;

    if (tid < 64) {
        int v = (tid < SCB) ? g_part[tid] : 0;
        int inc = v;
        #pragma unroll
        for (int d = 1; d < 32; d <<= 1) {
            int t = __shfl_up_sync(0xffffffffu, inc, d);
            if (lane >= d) inc += t;
        }
        if (lane == 31) winc[wid] = inc;
    }
    __syncthreads();
    if (tid < 64) {
        int v = (tid < SCB) ? g_part[tid] : 0;
        int inc = v;
        #pragma unroll
        for (int d = 1; d < 32; d <<= 1) {
            int t = __shfl_up_sync(0xffffffffu, inc, d);
            if (lane >= d) inc += t;
        }
        int off = (wid == 1) ? winc[0] : 0;
        sexcl[tid] = off + inc - v;
        if (tid == 63) stotal = winc[0] + winc[1];
    }
    __syncthreads();

    int i = blockIdx.x * 1024 + tid;
    int c = (i < NN) ? g_degcnt[i] : 0;
    int inc = c;
    #pragma unroll
    for (int d = 1; d < 32; d <<= 1) {
        int t = __shfl_up_sync(0xffffffffu, inc, d);
        if (lane >= d) inc += t;
    }
    if (lane == 31) winc[wid] = inc;
    __syncthreads();
    if (wid == 0) {
        int v = winc[lane];
        int vi = v;
        #pragma unroll
        for (int d = 1; d < 32; d <<= 1) {
            int t = __shfl_up_sync(0xffffffffu, vi, d);
            if (lane >= d) vi += t;
        }
        woff[lane] = vi - v;
    }
    __syncthreads();
    if (i < NN) {
        int run = sexcl[blockIdx.x] + woff[wid] + (inc - c);
        g_rowptr[i] = run;
        g_fill[i]   = run;
        g_invdeg[i] = 1.0f / (float)(c + 1);
    }
    if (blockIdx.x == 0 && tid == 0) g_rowptr[NN] = stotal;
}

// CSR fill, 1 edge/thread
__global__ void k_fill(const int* __restrict__ ei) {
    int e = blockIdx.x * blockDim.x + threadIdx.x;
    if (e < EE) {
        int r = ei[e];
        int c = ei[EE + e];
        if ((unsigned)r < NN && (unsigned)c < NN) {
            int p = atomicAdd(&g_fill[r], 1);
            if ((unsigned)p < EE) g_col[p] = c;
        }
    }
}

// ---------------------------------------------------------------------------
// Fused dropout-multiply + fp16 convert + GEMM:  z = (x*dm) @ W1
__global__ __launch_bounds__(256) void k_gemm_fused(const float* __restrict__ x,
                                                    const float* __restrict__ dm) {
    __shared__ __align__(16) __half As[64][KC + 8];
    __shared__ __align__(16) __half Bs[KC][HH + 8];
    int tid = threadIdx.x;
    int warp = tid >> 5, lane = tid & 31;
    int wm = warp >> 2;
    int wn = warp & 3;
    int m0 = blockIdx.x * 64;

    wmma::fragment<wmma::accumulator, 16, 16, 16, float> c[2][4];
    #pragma unroll
    for (int i = 0; i < 2; i++)
        #pragma unroll
        for (int j = 0; j < 4; j++) wmma::fill_fragment(c[i][j], 0.f);

    for (int kk = 0; kk < HH; kk += KC) {
        #pragma unroll
        for (int i = 0; i < 2; i++) {
            int idx = tid + i * 256;
            int row = idx >> 3;
            int c4  = (idx & 7) * 4;
            int grow = m0 + row;
            __half2 h0, h1;
            if (grow < NN) {
                float4 xv = *(const float4*)(x  + (size_t)grow * HH + kk + c4);
                float4 dv = *(const float4*)(dm + (size_t)grow * HH + kk + c4);
                h0 = __floats2half2_rn(xv.x*dv.x, xv.y*dv.y);
                h1 = __floats2half2_rn(xv.z*dv.z, xv.w*dv.w);
            } else {
                h0 = __floats2half2_rn(0.f, 0.f);
                h1 = h0;
            }
            *(__half2*)&As[row][c4]     = h0;
            *(__half2*)&As[row][c4 + 2] = h1;
        }
        #pragma unroll
        for (int i = 0; i < 4; i++) {
            int idx = tid + i * 256;
            int row = idx >> 5;
            int c8  = (idx & 31) * 8;
            *(uint4*)&Bs[row][c8] = *(const uint4*)(g_w1h + (size_t)(kk + row) * HH + c8);
        }
        __syncthreads();
        #pragma unroll
        for (int ks = 0; ks < KC; ks += 16) {
            wmma::fragment<wmma::matrix_a, 16, 16, 16, __half, wmma::row_major> a[2];
            #pragma unroll
            for (int i = 0; i < 2; i++)
                wmma::load_matrix_sync(a[i], &As[wm*32 + 16*i][ks], KC + 8);
            #pragma unroll
            for (int j = 0; j < 4; j++) {
                wmma::fragment<wmma::matrix_b, 16, 16, 16, __half, wmma::row_major> b;
                wmma::load_matrix_sync(b, &Bs[ks][wn*64 + 16*j], HH + 8);
                wmma::mma_sync(c[0][j], a[0], b, c[0][j]);
                wmma::mma_sync(c[1][j], a[1], b, c[1][j]);
            }
        }
        __syncthreads();
    }

    float* stg = (float*)Bs + warp * 320;
    #pragma unroll
    for (int i = 0; i < 2; i++)
        #pragma unroll
        for (int j = 0; j < 4; j++) {
            wmma::store_matrix_sync(stg, c[i][j], 20, wmma::mem_row_major);
            __syncwarp();
            if (lane < 16) {
                const float* sr = stg + lane * 20;
                __half2 hh[8];
                #pragma unroll
                for (int p = 0; p < 8; p++)
                    hh[p] = __floats2half2_rn(sr[2*p], sr[2*p+1]);
                int gr = m0 + wm*32 + i*16 + lane;
                __half* dst = g_z + (size_t)gr * HH + wn*64 + j*16;
                ((uint4*)dst)[0] = ((uint4*)hh)[0];
                ((uint4*)dst)[1] = ((uint4*)hh)[1];
            }
            __syncwarp();
        }
}

// ---------------------------------------------------------------------------
// half2 accumulate helpers
__device__ __forceinline__ void hacc4(__half2 a[4], uint4 raw) {
    __half2* h = (__half2*)&raw;
    a[0] = __hadd2(a[0], h[0]);
    a[1] = __hadd2(a[1], h[1]);
    a[2] = __hadd2(a[2], h[2]);
    a[3] = __hadd2(a[3], h[3]);
}
__device__ __forceinline__ void hfma4(__half2 a[4], uint4 raw, __half2 m) {
    __half2* h = (__half2*)&raw;
    a[0] = __hfma2(h[0], m, a[0]);
    a[1] = __hfma2(h[1], m, a[1]);
    a[2] = __hfma2(h[2], m, a[2]);
    a[3] = __hfma2(h[3], m, a[3]);
}
// scale (fp32) + evict-first store of 4 half2
__device__ __forceinline__ void store_h2x4_cs(__half* base, int lane, const __half2 a[4], float inv) {
    __half2 h[4];
    #pragma unroll
    for (int p = 0; p < 4; p++) {
        float2 f = __half22float2(a[p]);
        h[p] = __floats2half2_rn(f.x * inv, f.y * inv);
    }
    __stcs((uint4*)base + lane, *(uint4*)h);
}

// Fused first propagation step for all 4 views; HFMA2 (masks are exactly 0/1).
__global__ __launch_bounds__(256) void k_step1() {
    int gw = (blockIdx.x * blockDim.x + threadIdx.x) >> 5;
    int lane = threadIdx.x & 31;
    if (gw >= NN) return;
    int r = gw;

    uint4 sz = ((const uint4*)(g_z + (size_t)r * HH))[lane];
    __half2* szh = (__half2*)&sz;

    uint2 mr = g_mask4h[r];
    const __half* mrh = (const __half*)&mr;

    __half2 a[VV][4];
    #pragma unroll
    for (int v = 0; v < VV; v++) {
        __half2 mh = __half2half2(mrh[v]);
        #pragma unroll
        for (int k = 0; k < 4; k++) a[v][k] = __hmul2(szh[k], mh);
    }

    int jb = g_rowptr[r], je = g_rowptr[r + 1];
    int j = jb;
    for (; j + 1 < je; j += 2) {
        int c0 = g_col[j], c1 = g_col[j + 1];
        uint4 z0 = ((const uint4*)(g_z + (size_t)c0 * HH))[lane];
        uint4 z1 = ((const uint4*)(g_z + (size_t)c1 * HH))[lane];
        uint2 m0 = g_mask4h[c0];
        uint2 m1 = g_mask4h[c1];
        const __half* m0h = (const __half*)&m0;
        const __half* m1h = (const __half*)&m1;
        #pragma unroll
        for (int v = 0; v < VV; v++) {
            hfma4(a[v], z0, __half2half2(m0h[v]));
            hfma4(a[v], z1, __half2half2(m1h[v]));
        }
    }
    if (j < je) {
        int c = g_col[j];
        uint4 z0 = ((const uint4*)(g_z + (size_t)c * HH))[lane];
        uint2 m0 = g_mask4h[c];
        const __half* m0h = (const __half*)&m0;
        #pragma unroll
        for (int v = 0; v < VV; v++)
            hfma4(a[v], z0, __half2half2(m0h[v]));
    }
    float inv = g_invdeg[r];
    #pragma unroll
    for (int v = 0; v < VV; v++)
        store_h2x4_cs(g_pairs[v >> 1] + (size_t)r * PH + (v & 1) * HH, lane, a[v], inv);
}

// middle propagation step for one view-pair: pairs -> ptmp. HADD2 accumulation.
__global__ __launch_bounds__(256) void k_spmm2(int pair) {
    const __half* in = g_pairs[pair];
    __half* out      = g_ptmp[pair];

    int gw = (blockIdx.x * blockDim.x + threadIdx.x) >> 5;
    int lane = threadIdx.x & 31;
    if (gw >= NN) return;
    int r = gw;

    const uint4* sp = (const uint4*)(in + (size_t)r * PH);
    uint4 s0 = sp[lane], s1 = sp[lane + 32];
    __half2 a0[4], a1[4];
    *(uint4*)a0 = s0;
    *(uint4*)a1 = s1;

    int jb = g_rowptr[r], je = g_rowptr[r + 1];
    int j = jb;
    for (; j + 1 < je; j += 2) {
        int c0 = g_col[j], c1 = g_col[j + 1];
        const uint4* p0 = (const uint4*)(in + (size_t)c0 * PH);
        const uint4* p1 = (const uint4*)(in + (size_t)c1 * PH);
        uint4 r00 = p0[lane], r01 = p0[lane + 32];
        uint4 r10 = p1[lane], r11 = p1[lane + 32];
        hacc4(a0, r00); hacc4(a1, r01);
        hacc4(a0, r10); hacc4(a1, r11);
    }
    if (j < je) {
        int c = g_col[j];
        const uint4* p = (const uint4*)(in + (size_t)c * PH);
        uint4 u0 = p[lane], u1 = p[lane + 32];
        hacc4(a0, u0);
        hacc4(a1, u1);
    }
    float inv = g_invdeg[r];
    __half* orow = out + (size_t)r * PH;
    store_h2x4_cs(orow,      lane, a0, inv);
    store_h2x4_cs(orow + HH, lane, a1, inv);
}

// FINAL propagation step for one view-pair, fused with bias+relu+mean-pool.
// Reads ptmp[pair]; no global state store — pooled sums go straight to g_pool.
// Block = 8 warps = 8 consecutive nodes (NN = 6250 * 8 exactly).
__global__ __launch_bounds__(256) void k_spmm2f(int pair,
                                                const int* __restrict__ batch,
                                                const float* __restrict__ b1) {
    __shared__ float stage[8][2][HH];   // 16 KB
    __shared__ int   sbat[8];

    const __half* in = g_ptmp[pair];
    int tid = threadIdx.x;
    int w = tid >> 5, lane = tid & 31;
    int r0 = blockIdx.x * 8;
    int r = r0 + w;

    if (tid < 8) sbat[tid] = batch[r0 + tid];

    // --- spmm for node r ---
    const uint4* sp = (const uint4*)(in + (size_t)r * PH);
    uint4 s0 = sp[lane], s1 = sp[lane + 32];
    __half2 a0[4], a1[4];
    *(uint4*)a0 = s0;
    *(uint4*)a1 = s1;

    int jb = g_rowptr[r], je = g_rowptr[r + 1];
    int j = jb;
    for (; j + 1 < je; j += 2) {
        int c0 = g_col[j], c1 = g_col[j + 1];
        const uint4* p0 = (const uint4*)(in + (size_t)c0 * PH);
        const uint4* p1 = (const uint4*)(in + (size_t)c1 * PH);
        uint4 r00 = p0[lane], r01 = p0[lane + 32];
        uint4 r10 = p1[lane], r11 = p1[lane + 32];
        hacc4(a0, r00); hacc4(a1, r01);
        hacc4(a0, r10); hacc4(a1, r11);
    }
    if (j < je) {
        int c = g_col[j];
        const uint4* p = (const uint4*)(in + (size_t)c * PH);
        uint4 u0 = p[lane], u1 = p[lane + 32];
        hacc4(a0, u0);
        hacc4(a1, u1);
    }

    // --- bias + relu, stage to smem (fp32) ---
    float inv = g_invdeg[r];
    float4 bq0 = *(const float4*)(b1 + lane * 8);
    float4 bq1 = *(const float4*)(b1 + lane * 8 + 4);
    float bias[8] = {bq0.x, bq0.y, bq0.z, bq0.w, bq1.x, bq1.y, bq1.z, bq1.w};

    float f0[8], f1[8];
    #pragma unroll
    for (int p = 0; p < 4; p++) {
        float2 t0 = __half22float2(a0[p]);
        float2 t1 = __half22float2(a1[p]);
        f0[2*p]   = t0.x; f0[2*p+1] = t0.y;
        f1[2*p]   = t1.x; f1[2*p+1] = t1.y;
    }
    float* st0 = &stage[w][0][lane * 8];
    float* st1 = &stage[w][1][lane * 8];
    #pragma unroll
    for (int q = 0; q < 8; q++) {
        st0[q] = fmaxf(f0[q] * inv + bias[q], 0.f);
        st1[q] = fmaxf(f1[q] * inv + bias[q], 0.f);
    }
    __syncthreads();

    // --- run-length pool over the block's 8 sorted-batch nodes ---
    int f = tid;   // feature 0..255
    #pragma unroll
    for (int v = 0; v < 2; v++) {
        int vg = 2 * pair + v;
        float acc = 0.f;
        int cur = sbat[0];
        #pragma unroll
        for (int n = 0; n < 8; n++) {
            int b = sbat[n];
            if (b != cur) {
                if ((unsigned)cur < BB)
                    atomicAdd(&g_pool[(cur + vg * BB) * HH + f], acc);
                acc = 0.f; cur = b;
            }
            acc += stage[n][v][f];
        }
        if ((unsigned)cur < BB)
            atomicAdd(&g_pool[(cur + vg * BB) * HH + f], acc);
    }
}

// ---------------------------------------------------------------------------
__global__ __launch_bounds__(256) void k_head(const float* __restrict__ W2,
                                              const float* __restrict__ b2,
                                              const float* __restrict__ Wc,
                                              const float* __restrict__ bcv,
                                              float* __restrict__ out) {
    __shared__ float sp[HH];
    __shared__ float sy[HH];
    __shared__ float slog[CC];
    int vb = blockIdx.x;
    int v = vb >> 7, b = vb & 127;
    int tid = threadIdx.x;

    float cnt = (float)g_counts[b];
    if (cnt < 1.f) cnt = 1.f;
    sp[tid] = g_pool[(v * BB + b) * HH + tid] / cnt;
    __syncthreads();

    float acc = b2[tid];
    #pragma unroll 8
    for (int h = 0; h < HH; h++) acc += sp[h] * W2[h * HH + tid];
    sy[tid] = acc;
    __syncthreads();

    if (tid < CC) {
        float l = bcv[tid];
        #pragma unroll 8
        for (int h = 0; h < HH; h++) l += sy[h] * Wc[h * CC + tid];
        slog[tid] = l;
    }
    __syncthreads();

    if (tid == 0) {
        float mx = -1e30f;
        #pragma unroll
        for (int c = 0; c < CC; c++) mx = fmaxf(mx, slog[c]);
        float s = 0.f, e[CC];
        #pragma unroll
        for (int c = 0; c < CC; c++) { e[c] = expf(slog[c] - mx); s += e[c]; }
        float invs = 1.f / s;
        #pragma unroll
        for (int c = 0; c < CC; c++) g_probs[(v * BB + b) * CC + c] = e[c] * invs;
        if (v == 0) {
            #pragma unroll
            for (int c = 0; c < CC; c++) out[b * CC + c] = slog[c];
        }
    }
}

__global__ void k_loss(float* __restrict__ out, int out_size) {
    __shared__ float sc[BB], se[BB];
    int b = threadIdx.x;
    float mp[CC];
    #pragma unroll
    for (int c = 0; c < CC; c++) {
        float s = 0.f;
        #pragma unroll
        for (int v = 0; v < VV; v++) s += g_probs[(v * BB + b) * CC + c];
        mp[c] = s * (1.0f / VV);
    }
    float cons = 0.f;
    #pragma unroll
    for (int v = 0; v < VV; v++)
        #pragma unroll
        for (int c = 0; c < CC; c++) {
            float d = g_probs[(v * BB + b) * CC + c] - mp[c];
            cons += d * d;
        }
    float ent = 0.f;
    #pragma unroll
    for (int c = 0; c < CC; c++) ent -= mp[c] * logf(mp[c] + 1e-8f);
    sc[b] = cons; se[b] = ent;
    __syncthreads();
    for (int s = 64; s > 0; s >>= 1) {
        if (b < s) { sc[b] += sc[b + s]; se[b] += se[b + s]; }
        __syncthreads();
    }
    if (b == 0)
        out[out_size - 1] = 1.0f * (sc[0] / (float)(VV * BB)) + se[0] / (float)BB;
}

// ---------------------------------------------------------------------------
extern "C" void kernel_launch(void* const* d_in, const int* in_sizes, int n_in,
                              void* d_out, int out_size) {
    const float* x     = (const float*)d_in[0];
    const int*   ei    = (const int*)d_in[1];
    const int*   batch = (const int*)d_in[2];
    const float* dm    = (const float*)d_in[3];
    const float* masks = (const float*)d_in[4];
    const float* W1    = (const float*)d_in[5];
    const float* b1    = (const float*)d_in[6];
    const float* W2    = (const float*)d_in[7];
    const float* b2    = (const float*)d_in[8];
    const float* Wc    = (const float*)d_in[9];
    const float* bcv   = (const float*)d_in[10];
    float* out = (float*)d_out;

    // fork/join streams & events (host objects only; graph-capture-legal).
    cudaStream_t s2;
    cudaStreamCreate(&s2);
    cudaEvent_t eFork, eJoin;
    cudaEventCreateWithFlags(&eFork, cudaEventDisableTiming);
    cudaEventCreateWithFlags(&eJoin, cudaEventDisableTiming);

    // zero_main precedes zero_aux's atomic counts (g_counts zeroing).
    k_zero_main<<<(NN + 255) / 256, 256>>>();
    cudaEventRecord(eFork, 0);
    cudaStreamWaitEvent(s2, eFork, 0);

    // side arm: pool zero + W1 convert + counts + mask transpose, then GEMM
    k_zero_aux<<<(VV*BB*HH + 255) / 256, 256, 0, s2>>>(W1, batch, masks);
    k_gemm_fused<<<NPAD / 64, 256, 0, s2>>>(x, dm);
    cudaEventRecord(eJoin, s2);

    // main arm: CSR chain
    k_hist<<<(EE + 255) / 256, 256>>>(ei);
    k_scan_a<<<SCB, 1024>>>();
    k_scan_c<<<SCB, 1024>>>();
    k_fill<<<(EE + 255) / 256, 256>>>(ei);

    cudaStreamWaitEvent(0, eJoin, 0);                 // join before step1

    int wgrid = (NN * 32 + 255) / 256;                // warp per node

    k_step1<<<wgrid, 256>>>();
    k_spmm2 <<<wgrid, 256>>>(0);                      // pair0 step2
    k_spmm2f<<<NN / 8, 256>>>(0, batch, b1);          // pair0 step3 + pool
    k_spmm2 <<<wgrid, 256>>>(1);                      // pair1 step2
    k_spmm2f<<<NN / 8, 256>>>(1, batch, b1);          // pair1 step3 + pool

    k_head<<<VV * BB, 256>>>(W2, b2, Wc, bcv, out);
    k_loss<<<1, BB>>>(out, out_size);
}

// round 17
// speedup vs baseline: 1.2811x; 1.0059x over previous
#include <cuda_runtime.h>
#include <cuda_fp16.h>
#include <mma.h>
using namespace nvcuda;

#define NN 50000
#define NPAD 50048            // 782 * 64, pad for wmma tiles
#define EE 800000
#define HH 256
#define BB 128
#define VV 4
#define CC 10
#define PH 512                // pair row width: 2 views * 256 feats
#define KC 32                 // gemm k-chunk
#define SCB 49                // scan blocks: 49*1024 >= NN

// ---- scratch (device globals; no allocation allowed) ----
__device__ int    g_degcnt[NN];
__device__ int    g_rowptr[NN+1];
__device__ float  g_invdeg[NN];
__device__ int    g_col[EE];
__device__ int    g_epos[EE];               // per-edge within-row rank (from hist)
__device__ int    g_counts[BB];
__device__ int    g_part[SCB];              // scan partials (raw block sums)
__device__ uint2  g_mask4h[NN];             // node masks as 4 x half (exactly 0/1)
__device__ __half g_w1h[HH*HH];             // W1 fp16
__device__ __half g_z[NPAD*HH];             // (x*dropout) @ W1, fp16
__device__ __half g_pairs[2][(size_t)NN*PH]; // view pairs {0,1},{2,3}
__device__ __half g_ptmp[2][(size_t)NN*PH];  // ping-pong per pair
__device__ float  g_pool[VV*BB*HH];
__device__ float  g_probs[VV*BB*CC];

// ---------------------------------------------------------------------------
// main-stream zero: only what the CSR chain needs
__global__ void k_zero_main() {
    int i = blockIdx.x * blockDim.x + threadIdx.x;
    if (i < NN) g_degcnt[i] = 0;
    if (i < BB) g_counts[i] = 0;
}

// side-stream aux: pool zero + W1 convert + batch counts + mask transpose.
__global__ void k_zero_aux(const float* __restrict__ W1,
                           const int* __restrict__ batch,
                           const float* __restrict__ masks) {
    int i = blockIdx.x * blockDim.x + threadIdx.x;
    if (i < VV*BB*HH) g_pool[i] = 0.f;
    if (i < HH*HH/4) {
        float4 w = *(const float4*)(W1 + i * 4);
        __half2 h[2];
        h[0] = __floats2half2_rn(w.x, w.y);
        h[1] = __floats2half2_rn(w.z, w.w);
        *(uint2*)(g_w1h + i * 4) = *(uint2*)h;
    }
    if (i < NN) {
        int b = batch[i];
        if ((unsigned)b < BB) atomicAdd(&g_counts[b], 1);
        __half2 p01 = __floats2half2_rn(masks[i],        masks[NN + i]);
        __half2 p23 = __floats2half2_rn(masks[2*NN + i], masks[3*NN + i]);
        uint2 u;
        *(__half2*)&u.x = p01;
        *(__half2*)&u.y = p23;
        g_mask4h[i] = u;
    }
}

// edge-row histogram; captures each edge's within-row rank for atomic-free fill
__global__ void k_hist(const int* __restrict__ ei) {
    int e = blockIdx.x * blockDim.x + threadIdx.x;
    if (e < EE) {
        int r = ei[e];
        if ((unsigned)r < NN)
            g_epos[e] = atomicAdd(&g_degcnt[r], 1);
    }
}

// ---- 2-phase grid-wide exclusive scan of g_degcnt -------------------------
__global__ __launch_bounds__(1024) void k_scan_a() {
    __shared__ int wsum[32];
    int i = blockIdx.x * 1024 + threadIdx.x;
    int lane = threadIdx.x & 31, wid = threadIdx.x >> 5;
    int c = (i < NN) ? g_degcnt[i] : 0;
    int s = c;
    #pragma unroll
    for (int d = 16; d > 0; d >>= 1) s += __shfl_down_sync(0xffffffffu, s, d);
    if (lane == 0) wsum[wid] = s;
    __syncthreads();
    if (wid == 0) {
        int t = wsum[lane];
        #pragma unroll
        for (int d = 16; d > 0; d >>= 1) t += __shfl_down_sync(0xffffffffu, t, d);
        if (lane == 0) g_part[blockIdx.x] = t;
    }
}

__global__ __launch_bounds__(1024) void k_scan_c() {
    __shared__ int winc[32];
    __shared__ int woff[32];
    __shared__ int sexcl[64];
    __shared__ int stotal;
    int tid = threadIdx.x;
    int lane = tid & 31, wid = tid >> 5;

    if (tid < 64) {
        int v = (tid < SCB) ? g_part[tid] : 0;
        int inc = v;
        #pragma unroll
        for (int d = 1; d < 32; d <<= 1) {
            int t = __shfl_up_sync(0xffffffffu, inc, d);
            if (lane >= d) inc += t;
        }
        if (lane == 31) winc[wid] = inc;
    }
    __syncthreads();
    if (tid < 64) {
        int v = (tid < SCB) ? g_part[tid] : 0;
        int inc = v;
        #pragma unroll
        for (int d = 1; d < 32; d <<= 1) {
            int t = __shfl_up_sync(0xffffffffu, inc, d);
            if (lane >= d) inc += t;
        }
        int off = (wid == 1) ? winc[0] : 0;
        sexcl[tid] = off + inc - v;
        if (tid == 63) stotal = winc[0] + winc[1];
    }
    __syncthreads();

    int i = blockIdx.x * 1024 + tid;
    int c = (i < NN) ? g_degcnt[i] : 0;
    int inc = c;
    #pragma unroll
    for (int d = 1; d < 32; d <<= 1) {
        int t = __shfl_up_sync(0xffffffffu, inc, d);
        if (lane >= d) inc += t;
    }
    if (lane == 31) winc[wid] = inc;
    __syncthreads();
    if (wid == 0) {
        int v = winc[lane];
        int vi = v;
        #pragma unroll
        for (int d = 1; d < 32; d <<= 1) {
            int t = __shfl_up_sync(0xffffffffu, vi, d);
            if (lane >= d) vi += t;
        }
        woff[lane] = vi - v;
    }
    __syncthreads();
    if (i < NN) {
        int run = sexcl[blockIdx.x] + woff[wid] + (inc - c);
        g_rowptr[i] = run;
        g_invdeg[i] = 1.0f / (float)(c + 1);
    }
    if (blockIdx.x == 0 && tid == 0) g_rowptr[NN] = stotal;
}

// CSR fill, atomic-free: position = rowptr[r] + epos[e]
__global__ void k_fill(const int* __restrict__ ei) {
    int e = blockIdx.x * blockDim.x + threadIdx.x;
    if (e < EE) {
        int r = ei[e];
        int c = ei[EE + e];
        if ((unsigned)r < NN) {
            int p = g_rowptr[r] + g_epos[e];
            if ((unsigned)c >= NN) c = r;   // defensive: degrade to self loop
            if ((unsigned)p < EE) g_col[p] = c;
        }
    }
}

// ---------------------------------------------------------------------------
// Fused dropout-multiply + fp16 convert + GEMM:  z = (x*dm) @ W1
__global__ __launch_bounds__(256) void k_gemm_fused(const float* __restrict__ x,
                                                    const float* __restrict__ dm) {
    __shared__ __align__(16) __half As[64][KC + 8];
    __shared__ __align__(16) __half Bs[KC][HH + 8];
    int tid = threadIdx.x;
    int warp = tid >> 5, lane = tid & 31;
    int wm = warp >> 2;
    int wn = warp & 3;
    int m0 = blockIdx.x * 64;

    wmma::fragment<wmma::accumulator, 16, 16, 16, float> c[2][4];
    #pragma unroll
    for (int i = 0; i < 2; i++)
        #pragma unroll
        for (int j = 0; j < 4; j++) wmma::fill_fragment(c[i][j], 0.f);

    for (int kk = 0; kk < HH; kk += KC) {
        #pragma unroll
        for (int i = 0; i < 2; i++) {
            int idx = tid + i * 256;
            int row = idx >> 3;
            int c4  = (idx & 7) * 4;
            int grow = m0 + row;
            __half2 h0, h1;
            if (grow < NN) {
                float4 xv = *(const float4*)(x  + (size_t)grow * HH + kk + c4);
                float4 dv = *(const float4*)(dm + (size_t)grow * HH + kk + c4);
                h0 = __floats2half2_rn(xv.x*dv.x, xv.y*dv.y);
                h1 = __floats2half2_rn(xv.z*dv.z, xv.w*dv.w);
            } else {
                h0 = __floats2half2_rn(0.f, 0.f);
                h1 = h0;
            }
            *(__half2*)&As[row][c4]     = h0;
            *(__half2*)&As[row][c4 + 2] = h1;
        }
        #pragma unroll
        for (int i = 0; i < 4; i++) {
            int idx = tid + i * 256;
            int row = idx >> 5;
            int c8  = (idx & 31) * 8;
            *(uint4*)&Bs[row][c8] = *(const uint4*)(g_w1h + (size_t)(kk + row) * HH + c8);
        }
        __syncthreads();
        #pragma unroll
        for (int ks = 0; ks < KC; ks += 16) {
            wmma::fragment<wmma::matrix_a, 16, 16, 16, __half, wmma::row_major> a[2];
            #pragma unroll
            for (int i = 0; i < 2; i++)
                wmma::load_matrix_sync(a[i], &As[wm*32 + 16*i][ks], KC + 8);
            #pragma unroll
            for (int j = 0; j < 4; j++) {
                wmma::fragment<wmma::matrix_b, 16, 16, 16, __half, wmma::row_major> b;
                wmma::load_matrix_sync(b, &Bs[ks][wn*64 + 16*j], HH + 8);
                wmma::mma_sync(c[0][j], a[0], b, c[0][j]);
                wmma::mma_sync(c[1][j], a[1], b, c[1][j]);
            }
        }
        __syncthreads();
    }

    float* stg = (float*)Bs + warp * 320;
    #pragma unroll
    for (int i = 0; i < 2; i++)
        #pragma unroll
        for (int j = 0; j < 4; j++) {
            wmma::store_matrix_sync(stg, c[i][j], 20, wmma::mem_row_major);
            __syncwarp();
            if (lane < 16) {
                const float* sr = stg + lane * 20;
                __half2 hh[8];
                #pragma unroll
                for (int p = 0; p < 8; p++)
                    hh[p] = __floats2half2_rn(sr[2*p], sr[2*p+1]);
                int gr = m0 + wm*32 + i*16 + lane;
                __half* dst = g_z + (size_t)gr * HH + wn*64 + j*16;
                ((uint4*)dst)[0] = ((uint4*)hh)[0];
                ((uint4*)dst)[1] = ((uint4*)hh)[1];
            }
            __syncwarp();
        }
}

// ---------------------------------------------------------------------------
// half2 accumulate helpers
__device__ __forceinline__ void hacc4(__half2 a[4], uint4 raw) {
    __half2* h = (__half2*)&raw;
    a[0] = __hadd2(a[0], h[0]);
    a[1] = __hadd2(a[1], h[1]);
    a[2] = __hadd2(a[2], h[2]);
    a[3] = __hadd2(a[3], h[3]);
}
__device__ __forceinline__ void hfma4(__half2 a[4], uint4 raw, __half2 m) {
    __half2* h = (__half2*)&raw;
    a[0] = __hfma2(h[0], m, a[0]);
    a[1] = __hfma2(h[1], m, a[1]);
    a[2] = __hfma2(h[2], m, a[2]);
    a[3] = __hfma2(h[3], m, a[3]);
}
// scale (fp32) + store, evict-first variant (buffer NOT read by next pass)
__device__ __forceinline__ void store_h2x4_cs(__half* base, int lane, const __half2 a[4], float inv) {
    __half2 h[4];
    #pragma unroll
    for (int p = 0; p < 4; p++) {
        float2 f = __half22float2(a[p]);
        h[p] = __floats2half2_rn(f.x * inv, f.y * inv);
    }
    __stcs((uint4*)base + lane, *(uint4*)h);
}
// scale (fp32) + normal store (buffer IS the next pass's gather source)
__device__ __forceinline__ void store_h2x4(__half* base, int lane, const __half2 a[4], float inv) {
    __half2 h[4];
    #pragma unroll
    for (int p = 0; p < 4; p++) {
        float2 f = __half22float2(a[p]);
        h[p] = __floats2half2_rn(f.x * inv, f.y * inv);
    }
    ((uint4*)base)[lane] = *(uint4*)h;
}

// Fused first propagation step for all 4 views; HFMA2 (masks are exactly 0/1).
// pairs[0] stored normal (read next by spmm2(0)); pairs[1] evict-first.
__global__ __launch_bounds__(256) void k_step1() {
    int gw = (blockIdx.x * blockDim.x + threadIdx.x) >> 5;
    int lane = threadIdx.x & 31;
    if (gw >= NN) return;
    int r = gw;

    uint4 sz = ((const uint4*)(g_z + (size_t)r * HH))[lane];
    __half2* szh = (__half2*)&sz;

    uint2 mr = g_mask4h[r];
    const __half* mrh = (const __half*)&mr;

    __half2 a[VV][4];
    #pragma unroll
    for (int v = 0; v < VV; v++) {
        __half2 mh = __half2half2(mrh[v]);
        #pragma unroll
        for (int k = 0; k < 4; k++) a[v][k] = __hmul2(szh[k], mh);
    }

    int jb = g_rowptr[r], je = g_rowptr[r + 1];
    int j = jb;
    for (; j + 1 < je; j += 2) {
        int c0 = g_col[j], c1 = g_col[j + 1];
        uint4 z0 = ((const uint4*)(g_z + (size_t)c0 * HH))[lane];
        uint4 z1 = ((const uint4*)(g_z + (size_t)c1 * HH))[lane];
        uint2 m0 = g_mask4h[c0];
        uint2 m1 = g_mask4h[c1];
        const __half* m0h = (const __half*)&m0;
        const __half* m1h = (const __half*)&m1;
        #pragma unroll
        for (int v = 0; v < VV; v++) {
            hfma4(a[v], z0, __half2half2(m0h[v]));
            hfma4(a[v], z1, __half2half2(m1h[v]));
        }
    }
    if (j < je) {
        int c = g_col[j];
        uint4 z0 = ((const uint4*)(g_z + (size_t)c * HH))[lane];
        uint2 m0 = g_mask4h[c];
        const __half* m0h = (const __half*)&m0;
        #pragma unroll
        for (int v = 0; v < VV; v++)
            hfma4(a[v], z0, __half2half2(m0h[v]));
    }
    float inv = g_invdeg[r];
    store_h2x4   (g_pairs[0] + (size_t)r * PH,      lane, a[0], inv);
    store_h2x4   (g_pairs[0] + (size_t)r * PH + HH, lane, a[1], inv);
    store_h2x4_cs(g_pairs[1] + (size_t)r * PH,      lane, a[2], inv);
    store_h2x4_cs(g_pairs[1] + (size_t)r * PH + HH, lane, a[3], inv);
}

// middle propagation step for one view-pair: pairs -> ptmp. HADD2 accumulation.
// ptmp stored normal: it is the gather source of the immediately-following spmm2f.
__global__ __launch_bounds__(256) void k_spmm2(int pair) {
    const __half* in = g_pairs[pair];
    __half* out      = g_ptmp[pair];

    int gw = (blockIdx.x * blockDim.x + threadIdx.x) >> 5;
    int lane = threadIdx.x & 31;
    if (gw >= NN) return;
    int r = gw;

    const uint4* sp = (const uint4*)(in + (size_t)r * PH);
    uint4 s0 = sp[lane], s1 = sp[lane + 32];
    __half2 a0[4], a1[4];
    *(uint4*)a0 = s0;
    *(uint4*)a1 = s1;

    int jb = g_rowptr[r], je = g_rowptr[r + 1];
    int j = jb;
    for (; j + 1 < je; j += 2) {
        int c0 = g_col[j], c1 = g_col[j + 1];
        const uint4* p0 = (const uint4*)(in + (size_t)c0 * PH);
        const uint4* p1 = (const uint4*)(in + (size_t)c1 * PH);
        uint4 r00 = p0[lane], r01 = p0[lane + 32];
        uint4 r10 = p1[lane], r11 = p1[lane + 32];
        hacc4(a0, r00); hacc4(a1, r01);
        hacc4(a0, r10); hacc4(a1, r11);
    }
    if (j < je) {
        int c = g_col[j];
        const uint4* p = (const uint4*)(in + (size_t)c * PH);
        uint4 u0 = p[lane], u1 = p[lane + 32];
        hacc4(a0, u0);
        hacc4(a1, u1);
    }
    float inv = g_invdeg[r];
    __half* orow = out + (size_t)r * PH;
    store_h2x4(orow,      lane, a0, inv);
    store_h2x4(orow + HH, lane, a1, inv);
}

// FINAL propagation step for one view-pair, fused with bias+relu+mean-pool.
__global__ __launch_bounds__(256) void k_spmm2f(int pair,
                                                const int* __restrict__ batch,
                                                const float* __restrict__ b1) {
    __shared__ float stage[8][2][HH];   // 16 KB
    __shared__ int   sbat[8];

    const __half* in = g_ptmp[pair];
    int tid = threadIdx.x;
    int w = tid >> 5, lane = tid & 31;
    int r0 = blockIdx.x * 8;
    int r = r0 + w;

    if (tid < 8) sbat[tid] = batch[r0 + tid];

    // --- spmm for node r ---
    const uint4* sp = (const uint4*)(in + (size_t)r * PH);
    uint4 s0 = sp[lane], s1 = sp[lane + 32];
    __half2 a0[4], a1[4];
    *(uint4*)a0 = s0;
    *(uint4*)a1 = s1;

    int jb = g_rowptr[r], je = g_rowptr[r + 1];
    int j = jb;
    for (; j + 1 < je; j += 2) {
        int c0 = g_col[j], c1 = g_col[j + 1];
        const uint4* p0 = (const uint4*)(in + (size_t)c0 * PH);
        const uint4* p1 = (const uint4*)(in + (size_t)c1 * PH);
        uint4 r00 = p0[lane], r01 = p0[lane + 32];
        uint4 r10 = p1[lane], r11 = p1[lane + 32];
        hacc4(a0, r00); hacc4(a1, r01);
        hacc4(a0, r10); hacc4(a1, r11);
    }
    if (j < je) {
        int c = g_col[j];
        const uint4* p = (const uint4*)(in + (size_t)c * PH);
        uint4 u0 = p[lane], u1 = p[lane + 32];
        hacc4(a0, u0);
        hacc4(a1, u1);
    }

    // --- bias + relu, stage to smem (fp32) ---
    float inv = g_invdeg[r];
    float4 bq0 = *(const float4*)(b1 + lane * 8);
    float4 bq1 = *(const float4*)(b1 + lane * 8 + 4);
    float bias[8] = {bq0.x, bq0.y, bq0.z, bq0.w, bq1.x, bq1.y, bq1.z, bq1.w};

    float f0[8], f1[8];
    #pragma unroll
    for (int p = 0; p < 4; p++) {
        float2 t0 = __half22float2(a0[p]);
        float2 t1 = __half22float2(a1[p]);
        f0[2*p]   = t0.x; f0[2*p+1] = t0.y;
        f1[2*p]   = t1.x; f1[2*p+1] = t1.y;
    }
    float* st0 = &stage[w][0][lane * 8];
    float* st1 = &stage[w][1][lane * 8];
    #pragma unroll
    for (int q = 0; q < 8; q++) {
        st0[q] = fmaxf(f0[q] * inv + bias[q], 0.f);
        st1[q] = fmaxf(f1[q] * inv + bias[q], 0.f);
    }
    __syncthreads();

    // --- run-length pool over the block's 8 sorted-batch nodes ---
    int f = tid;   // feature 0..255
    #pragma unroll
    for (int v = 0; v < 2; v++) {
        int vg = 2 * pair + v;
        float acc = 0.f;
        int cur = sbat[0];
        #pragma unroll
        for (int n = 0; n < 8; n++) {
            int b = sbat[n];
            if (b != cur) {
                if ((unsigned)cur < BB)
                    atomicAdd(&g_pool[(cur + vg * BB) * HH + f], acc);
                acc = 0.f; cur = b;
            }
            acc += stage[n][v][f];
        }
        if ((unsigned)cur < BB)
            atomicAdd(&g_pool[(cur + vg * BB) * HH + f], acc);
    }
}

// ---------------------------------------------------------------------------
__global__ __launch_bounds__(256) void k_head(const float* __restrict__ W2,
                                              const float* __restrict__ b2,
                                              const float* __restrict__ Wc,
                                              const float* __restrict__ bcv,
                                              float* __restrict__ out) {
    __shared__ float sp[HH];
    __shared__ float sy[HH];
    __shared__ float slog[CC];
    int vb = blockIdx.x;
    int v = vb >> 7, b = vb & 127;
    int tid = threadIdx.x;

    float cnt = (float)g_counts[b];
    if (cnt < 1.f) cnt = 1.f;
    sp[tid] = g_pool[(v * BB + b) * HH + tid] / cnt;
    __syncthreads();

    float acc = b2[tid];
    #pragma unroll 8
    for (int h = 0; h < HH; h++) acc += sp[h] * W2[h * HH + tid];
    sy[tid] = acc;
    __syncthreads();

    if (tid < CC) {
        float l = bcv[tid];
        #pragma unroll 8
        for (int h = 0; h < HH; h++) l += sy[h] * Wc[h * CC + tid];
        slog[tid] = l;
    }
    __syncthreads();

    if (tid == 0) {
        float mx = -1e30f;
        #pragma unroll
        for (int c = 0; c < CC; c++) mx = fmaxf(mx, slog[c]);
        float s = 0.f, e[CC];
        #pragma unroll
        for (int c = 0; c < CC; c++) { e[c] = expf(slog[c] - mx); s += e[c]; }
        float invs = 1.f / s;
        #pragma unroll
        for (int c = 0; c < CC; c++) g_probs[(v * BB + b) * CC + c] = e[c] * invs;
        if (v == 0) {
            #pragma unroll
            for (int c = 0; c < CC; c++) out[b * CC + c] = slog[c];
        }
    }
}

__global__ void k_loss(float* __restrict__ out, int out_size) {
    __shared__ float sc[BB], se[BB];
    int b = threadIdx.x;
    float mp[CC];
    #pragma unroll
    for (int c = 0; c < CC; c++) {
        float s = 0.f;
        #pragma unroll
        for (int v = 0; v < VV; v++) s += g_probs[(v * BB + b) * CC + c];
        mp[c] = s * (1.0f / VV);
    }
    float cons = 0.f;
    #pragma unroll
    for (int v = 0; v < VV; v++)
        #pragma unroll
        for (int c = 0; c < CC; c++) {
            float d = g_probs[(v * BB + b) * CC + c] - mp[c];
            cons += d * d;
        }
    float ent = 0.f;
    #pragma unroll
    for (int c = 0; c < CC; c++) ent -= mp[c] * logf(mp[c] + 1e-8f);
    sc[b] = cons; se[b] = ent;
    __syncthreads();
    for (int s = 64; s > 0; s >>= 1) {
        if (b < s) { sc[b] += sc[b + s]; se[b] += se[b + s]; }
        __syncthreads();
    }
    if (b == 0)
        out[out_size - 1] = 1.0f * (sc[0] / (float)(VV * BB)) + se[0] / (float)BB;
}

// ---------------------------------------------------------------------------
extern "C" void kernel_launch(void* const* d_in, const int* in_sizes, int n_in,
                              void* d_out, int out_size) {
    const float* x     = (const float*)d_in[0];
    const int*   ei    = (const int*)d_in[1];
    const int*   batch = (const int*)d_in[2];
    const float* dm    = (const float*)d_in[3];
    const float* masks = (const float*)d_in[4];
    const float* W1    = (const float*)d_in[5];
    const float* b1    = (const float*)d_in[6];
    const float* W2    = (const float*)d_in[7];
    const float* b2    = (const float*)d_in[8];
    const float* Wc    = (const float*)d_in[9];
    const float* bcv   = (const float*)d_in[10];
    float* out = (float*)d_out;

    // fork/join streams & events (host objects only; graph-capture-legal).
    cudaStream_t s2;
    cudaStreamCreate(&s2);
    cudaEvent_t eFork, eJoin;
    cudaEventCreateWithFlags(&eFork, cudaEventDisableTiming);
    cudaEventCreateWithFlags(&eJoin, cudaEventDisableTiming);

    // zero_main precedes zero_aux's atomic counts (g_counts zeroing).
    k_zero_main<<<(NN + 255) / 256, 256>>>();
    cudaEventRecord(eFork, 0);
    cudaStreamWaitEvent(s2, eFork, 0);

    // side arm: pool zero + W1 convert + counts + mask transpose, then GEMM
    k_zero_aux<<<(VV*BB*HH + 255) / 256, 256, 0, s2>>>(W1, batch, masks);
    k_gemm_fused<<<NPAD / 64, 256, 0, s2>>>(x, dm);
    cudaEventRecord(eJoin, s2);

    // main arm: CSR chain
    k_hist<<<(EE + 255) / 256, 256>>>(ei);
    k_scan_a<<<SCB, 1024>>>();
    k_scan_c<<<SCB, 1024>>>();
    k_fill<<<(EE + 255) / 256, 256>>>(ei);

    cudaStreamWaitEvent(0, eJoin, 0);                 // join before step1

    int wgrid = (NN * 32 + 255) / 256;                // warp per node

    k_step1<<<wgrid, 256>>>();
    k_spmm2 <<<wgrid, 256>>>(0);                      // pair0 step2
    k_spmm2f<<<NN / 8, 256>>>(0, batch, b1);          // pair0 step3 + pool
    k_spmm2 <<<wgrid, 256>>>(1);                      // pair1 step2
    k_spmm2f<<<NN / 8, 256>>>(1, batch, b1);          // pair1 step3 + pool

    k_head<<<VV * BB, 256>>>(W2, b2, Wc, bcv, out);
    k_loss<<<1, BB>>>(out, out_size);
}